// round 1
// baseline (speedup 1.0000x reference)
#include <cuda_runtime.h>
#include <math.h>

// ---------------- problem constants ----------------
#define NC    8          // clusters / experts
#define HD    256        // hidden dim
#define DIN   36         // posenc input dim (3*2*6)
#define NMID  3          // mid layers
#define NMAX  65536      // max points (actual N from in_sizes)
#define TM    64         // points per CTA
#define NTHR  256        // threads per CTA
#define ASTRIDE 260      // activation row stride (pad 256 -> 260 to break bank patterns)
#define WSTRIDE 33       // weight tile row stride (32 + 1, conflict-free)
#define WS_FLOATS (HD * WSTRIDE)   // 8448

// ---------------- device scratch (static: no cudaMalloc allowed) ----------------
__device__ float d_Win [NC * HD * DIN];          // normalized input weights
__device__ float d_Wmid[NC * NMID * HD * HD];    // normalized mid weights (6.3 MB)
__device__ float d_Wout[NC * NMID * HD];         // normalized output weights [C][3][H]
__device__ int   d_sorted[NMAX];
__device__ int   d_hist[NC];
__device__ int   d_cursor[NC];
__device__ int   d_off[NC + 1];
__device__ int   d_blkoff[NC + 1];

// ---------------- tiny setup kernels ----------------
__global__ void initK() {
    if (threadIdx.x < NC) d_hist[threadIdx.x] = 0;
}

__global__ void histK(const int* __restrict__ cid, int n) {
    __shared__ int lh[NC];
    if (threadIdx.x < NC) lh[threadIdx.x] = 0;
    __syncthreads();
    for (int i = blockIdx.x * blockDim.x + threadIdx.x; i < n; i += gridDim.x * blockDim.x)
        atomicAdd(&lh[cid[i]], 1);
    __syncthreads();
    if (threadIdx.x < NC) atomicAdd(&d_hist[threadIdx.x], lh[threadIdx.x]);
}

__global__ void prefixK() {
    if (threadIdx.x == 0) {
        int o = 0, bo = 0;
        for (int c = 0; c < NC; c++) {
            d_off[c] = o; d_cursor[c] = o; d_blkoff[c] = bo;
            o  += d_hist[c];
            bo += (d_hist[c] + TM - 1) / TM;
        }
        d_off[NC] = o; d_blkoff[NC] = bo;
    }
}

__global__ void scatterK(const int* __restrict__ cid, int n) {
    __shared__ int lh[NC], base[NC];
    if (threadIdx.x < NC) lh[threadIdx.x] = 0;
    __syncthreads();
    int i = blockIdx.x * blockDim.x + threadIdx.x;
    int c = -1, r = 0;
    if (i < n) { c = cid[i]; r = atomicAdd(&lh[c], 1); }
    __syncthreads();
    if (threadIdx.x < NC) base[threadIdx.x] = atomicAdd(&d_cursor[threadIdx.x], lh[threadIdx.x]);
    __syncthreads();
    if (i < n) d_sorted[base[c] + r] = i;
}

// ---------------- weight normalization: W = g[row] * V[row] / ||V[row]|| ----------------
__device__ __forceinline__ void rownorm_body(const float* __restrict__ V,
                                             const float* __restrict__ g,
                                             float* __restrict__ W, int rows, int K) {
    int row  = blockIdx.x * 8 + (threadIdx.x >> 5);
    int lane = threadIdx.x & 31;
    if (row >= rows) return;
    const float* v = V + (size_t)row * K;
    float s = 0.f;
    for (int k = lane; k < K; k += 32) { float x = v[k]; s = fmaf(x, x, s); }
    #pragma unroll
    for (int off = 16; off; off >>= 1) s += __shfl_xor_sync(0xffffffffu, s, off);
    float scale = g[row] * rsqrtf(s);
    float* w = W + (size_t)row * K;
    for (int k = lane; k < K; k += 32) w[k] = v[k] * scale;
}

__global__ void normWinK (const float* V, const float* g) { rownorm_body(V, g, d_Win,  NC * HD,        DIN); }
__global__ void normWmidK(const float* V, const float* g) { rownorm_body(V, g, d_Wmid, NC * NMID * HD, HD ); }
__global__ void normWoutK(const float* V, const float* g) { rownorm_body(V, g, d_Wout, NC * NMID,      HD ); }

// ---------------- fused MLP ----------------
// One CTA = TM(64) points of one cluster. 256 threads = 16(tx: n) x 16(ty: m-groups).
// Each thread: acc[4 m][16 n] register tile. Weights staged in SMEM per 32-wide K chunk.
__device__ __forceinline__ void gemm_relu(const float* __restrict__ Wg,   // [HD][K] row-major
                                          const float* __restrict__ bias, // [HD]
                                          const float* __restrict__ src,  // [TM][ASTRIDE]
                                          float* __restrict__ dst,        // [TM][ASTRIDE]
                                          float* __restrict__ Ws, int K) {
    const int t  = threadIdx.x;
    const int tx = t & 15;
    const int ty = t >> 4;

    float acc[4][16];
    #pragma unroll
    for (int i = 0; i < 4; i++)
        #pragma unroll
        for (int j = 0; j < 16; j++) acc[i][j] = 0.f;

    for (int kc = 0; kc < K; kc += 32) {
        const int KT = min(32, K - kc);
        // stage weight chunk: Ws[n][kk] = Wg[n][kc+kk], stride 33 (conflict-free reads)
        for (int s = t; s < HD * KT; s += NTHR) {
            int nn = s / KT, kk = s - nn * KT;
            Ws[nn * WSTRIDE + kk] = Wg[nn * K + kc + kk];
        }
        __syncthreads();
        #pragma unroll 2
        for (int kk = 0; kk < KT; kk++) {
            float a0 = src[(ty * 4 + 0) * ASTRIDE + kc + kk];
            float a1 = src[(ty * 4 + 1) * ASTRIDE + kc + kk];
            float a2 = src[(ty * 4 + 2) * ASTRIDE + kc + kk];
            float a3 = src[(ty * 4 + 3) * ASTRIDE + kc + kk];
            #pragma unroll
            for (int jj = 0; jj < 16; jj++) {
                float w = Ws[(tx + 16 * jj) * WSTRIDE + kk];
                acc[0][jj] = fmaf(a0, w, acc[0][jj]);
                acc[1][jj] = fmaf(a1, w, acc[1][jj]);
                acc[2][jj] = fmaf(a2, w, acc[2][jj]);
                acc[3][jj] = fmaf(a3, w, acc[3][jj]);
            }
        }
        __syncthreads();
    }
    // epilogue: bias + ReLU -> dst
    #pragma unroll
    for (int jj = 0; jj < 16; jj++) {
        int nn = tx + 16 * jj;
        float bb = bias[nn];
        #pragma unroll
        for (int ii = 0; ii < 4; ii++) {
            float v = acc[ii][jj] + bb;
            dst[(ty * 4 + ii) * ASTRIDE + nn] = fmaxf(v, 0.f);
        }
    }
}

__global__ void __launch_bounds__(NTHR, 1)
mlpK(const float* __restrict__ X,
     const float* __restrict__ b_in,
     const float* __restrict__ b_mid,
     const float* __restrict__ b_out,
     float* __restrict__ out, int n) {
    extern __shared__ float smem[];
    float* A     = smem;                    // TM x ASTRIDE
    float* B     = A + TM * ASTRIDE;        // TM x ASTRIDE
    float* Ws    = B + TM * ASTRIDE;        // WS_FLOATS
    float* WoutS = Ws + WS_FLOATS;          // 3 x HD
    int*   idxS  = (int*)(WoutS + NMID * HD); // TM

    int b = blockIdx.x;
    if (b >= d_blkoff[NC]) return;
    int c = 0;
    while (b >= d_blkoff[c + 1]) c++;
    int start = d_off[c] + (b - d_blkoff[c]) * TM;
    int cnt   = d_off[c + 1] - start;
    if (cnt > TM) cnt = TM;

    const int t = threadIdx.x;
    if (t < TM) idxS[t] = (t < cnt) ? d_sorted[start + t] : -1;
    __syncthreads();

    // positional encoding into A (cols [0,36))
    if (t < TM) {
        float* row = A + t * ASTRIDE;
        int id = idxS[t];
        if (id >= 0) {
            float x = X[3 * id], y = X[3 * id + 1], z = X[3 * id + 2];
            float f = 1.f;
            #pragma unroll
            for (int fi = 0; fi < 6; fi++) {
                float s0, c0, s1, c1, s2, c2;
                sincosf(x * f, &s0, &c0);
                sincosf(y * f, &s1, &c1);
                sincosf(z * f, &s2, &c2);
                row[fi * 6 + 0] = s0; row[fi * 6 + 1] = s1; row[fi * 6 + 2] = s2;
                row[fi * 6 + 3] = c0; row[fi * 6 + 4] = c1; row[fi * 6 + 5] = c2;
                f *= 2.f;
            }
        } else {
            #pragma unroll
            for (int k = 0; k < DIN; k++) row[k] = 0.f;
        }
    }
    __syncthreads();

    gemm_relu(d_Win  + (size_t)c * HD * DIN,             b_in  +  c * HD,             A, B, Ws, DIN);
    gemm_relu(d_Wmid + (size_t)(c * NMID + 0) * HD * HD, b_mid + (c * NMID + 0) * HD, B, A, Ws, HD);
    gemm_relu(d_Wmid + (size_t)(c * NMID + 1) * HD * HD, b_mid + (c * NMID + 1) * HD, A, B, Ws, HD);
    gemm_relu(d_Wmid + (size_t)(c * NMID + 2) * HD * HD, b_mid + (c * NMID + 2) * HD, B, A, Ws, HD);
    // final activations in A

    // output layer: 3 rows of 256, warp-per-output dot products + tanh + scatter
    for (int s = t; s < NMID * HD; s += NTHR) WoutS[s] = d_Wout[c * NMID * HD + s];
    __syncthreads();

    int lane = t & 31, w = t >> 5;
    #pragma unroll
    for (int q = 0; q < 24; q++) {          // 8 warps x 24 = 192 = 64 points x 3 outputs
        int o = w * 24 + q;
        int m = o / 3, j = o - 3 * m;
        const float* arow = A + m * ASTRIDE;
        const float* wrow = WoutS + j * HD;
        float s = 0.f;
        #pragma unroll
        for (int k = lane; k < HD; k += 32) s = fmaf(arow[k], wrow[k], s);
        #pragma unroll
        for (int off = 16; off; off >>= 1) s += __shfl_xor_sync(0xffffffffu, s, off);
        if (lane == 0 && m < cnt)
            out[3 * idxS[m] + j] = tanhf(s + b_out[c * NMID + j]);
    }
}

// ---------------- launch ----------------
static const int SMEM_BYTES = (TM * ASTRIDE * 2 + WS_FLOATS + NMID * HD + TM) * (int)sizeof(float);

extern "C" void kernel_launch(void* const* d_in, const int* in_sizes, int n_in,
                              void* d_out, int out_size) {
    const float* X     = (const float*)d_in[0];
    const int*   cid   = (const int*)  d_in[1];
    const float* V_in  = (const float*)d_in[2];
    const float* g_in  = (const float*)d_in[3];
    const float* b_in  = (const float*)d_in[4];
    const float* V_mid = (const float*)d_in[5];
    const float* g_mid = (const float*)d_in[6];
    const float* b_mid = (const float*)d_in[7];
    const float* V_out = (const float*)d_in[8];
    const float* g_out = (const float*)d_in[9];
    const float* b_out = (const float*)d_in[10];
    float* out = (float*)d_out;
    const int n = in_sizes[0] / 3;

    cudaFuncSetAttribute(mlpK, cudaFuncAttributeMaxDynamicSharedMemorySize, SMEM_BYTES);

    initK<<<1, 32>>>();
    histK<<<256, 256>>>(cid, n);
    prefixK<<<1, 1>>>();
    scatterK<<<(n + 255) / 256, 256>>>(cid, n);

    normWinK <<<(NC * HD        + 7) / 8, 256>>>(V_in,  g_in);
    normWmidK<<<(NC * NMID * HD + 7) / 8, 256>>>(V_mid, g_mid);
    normWoutK<<<(NC * NMID      + 7) / 8, 256>>>(V_out, g_out);

    const int blocks = (n + TM - 1) / TM + NC;
    mlpK<<<blocks, NTHR, SMEM_BYTES>>>(X, b_in, b_mid, b_out, out, n);
}

// round 6
// speedup vs baseline: 2.4943x; 2.4943x over previous
#include <cuda_runtime.h>
#include <cuda_bf16.h>
#include <math.h>
#include <stdint.h>

// ---------------- problem constants ----------------
#define NC    8
#define HD    256
#define DIN   36
#define NMID  3
#define NMAX  65536
#define TM    128          // points per CTA
#define NTHR  512          // 16 warps: 4 (m) x 4 (n)

#define KCH       32       // K chunk
#define NCHUNK    24       // 3 mid layers x 8 chunks
#define BROW      80       // B SMEM row stride bytes (20 words -> conflict-free)
#define CHUNK_B   (HD * BROW)          // 20480 per split
#define CHUNK_BYTES (2 * CHUNK_B)      // hi + lo = 40960
#define AROW      528      // A SMEM row stride bytes (132 words -> conflict-free)
#define HROW      264      // final fp32 hidden row stride (floats): 128*264*4 = 135168 B fits A region

// SMEM layout (bytes)
#define SM_AHI   0
#define SM_ALO   (SM_AHI + TM * AROW)            // 67584
#define SM_B     (SM_ALO + TM * AROW)            // 135168  (2 x 40960)
#define SM_WS    SM_B                            // overlay: Win slice 256x37 fp32 (37888)
#define SM_P     (SM_B + 256 * 37 * 4)           // overlay: posenc 128x40 fp32 (20480)
#define SM_BIAS  (SM_B + 2 * CHUNK_BYTES)        // 217088  (3*256 floats, mid biases)
#define SM_BIN   (SM_BIAS + NMID * HD * 4)       // 220160  (256 floats, b_in)
#define SM_WOUT  (SM_BIN + HD * 4)               // 221184  (3*256 floats)
#define SM_BOUT  (SM_WOUT + 3 * HD * 4)          // 224256  (4 floats)
#define SM_IDX   (SM_BOUT + 16)                  // 224272  (128 ints)
#define SMEM_BYTES (SM_IDX + TM * 4)             // 224784

// ---------------- device scratch ----------------
__device__ float d_Win [NC * HD * DIN];
__device__ float d_Wmid[NC * NMID * HD * HD];
__device__ float d_Wout[NC * NMID * HD];
__device__ __align__(128) unsigned char d_Wpk[NC * NCHUNK * CHUNK_BYTES];
__device__ int   d_sorted[NMAX];
__device__ int   d_hist[NC];
__device__ int   d_cursor[NC];
__device__ int   d_off[NC + 1];
__device__ int   d_blkoff[NC + 1];

// ---------------- setup kernels ----------------
__global__ void initK() { if (threadIdx.x < NC) d_hist[threadIdx.x] = 0; }

__global__ void histK(const int* __restrict__ cid, int n) {
    __shared__ int lh[NC];
    if (threadIdx.x < NC) lh[threadIdx.x] = 0;
    __syncthreads();
    for (int i = blockIdx.x * blockDim.x + threadIdx.x; i < n; i += gridDim.x * blockDim.x)
        atomicAdd(&lh[cid[i]], 1);
    __syncthreads();
    if (threadIdx.x < NC) atomicAdd(&d_hist[threadIdx.x], lh[threadIdx.x]);
}

__global__ void prefixK() {
    if (threadIdx.x == 0) {
        int o = 0, bo = 0;
        for (int c = 0; c < NC; c++) {
            d_off[c] = o; d_cursor[c] = o; d_blkoff[c] = bo;
            o  += d_hist[c];
            bo += (d_hist[c] + TM - 1) / TM;
        }
        d_off[NC] = o; d_blkoff[NC] = bo;
    }
}

__global__ void scatterK(const int* __restrict__ cid, int n) {
    __shared__ int lh[NC], base[NC];
    if (threadIdx.x < NC) lh[threadIdx.x] = 0;
    __syncthreads();
    int i = blockIdx.x * blockDim.x + threadIdx.x;
    int c = -1, r = 0;
    if (i < n) { c = cid[i]; r = atomicAdd(&lh[c], 1); }
    __syncthreads();
    if (threadIdx.x < NC) base[threadIdx.x] = atomicAdd(&d_cursor[threadIdx.x], lh[threadIdx.x]);
    __syncthreads();
    if (i < n) d_sorted[base[c] + r] = i;
}

// weight_norm: W = g[row] * V[row] / ||V[row]||
__device__ __forceinline__ void rownorm_body(const float* __restrict__ V,
                                             const float* __restrict__ g,
                                             float* __restrict__ W, int rows, int K) {
    int row  = blockIdx.x * 8 + (threadIdx.x >> 5);
    int lane = threadIdx.x & 31;
    if (row >= rows) return;
    const float* v = V + (size_t)row * K;
    float s = 0.f;
    for (int k = lane; k < K; k += 32) { float x = v[k]; s = fmaf(x, x, s); }
    #pragma unroll
    for (int off = 16; off; off >>= 1) s += __shfl_xor_sync(0xffffffffu, s, off);
    float scale = g[row] * rsqrtf(s);
    float* w = W + (size_t)row * K;
    for (int k = lane; k < K; k += 32) w[k] = v[k] * scale;
}

__global__ void normWinK (const float* V, const float* g) { rownorm_body(V, g, d_Win,  NC * HD,        DIN); }
__global__ void normWmidK(const float* V, const float* g) { rownorm_body(V, g, d_Wmid, NC * NMID * HD, HD ); }
__global__ void normWoutK(const float* V, const float* g) { rownorm_body(V, g, d_Wout, NC * NMID,      HD ); }

// pack split-bf16 MID weights into SMEM-image chunks: [hi 20480][lo 20480]
__global__ void packK() {
    int t = blockIdx.x * 256 + threadIdx.x;
    const int total = NC * NCHUNK * HD * KCH;
    if (t >= total) return;
    int k  = t & (KCH - 1);
    int r  = (t >> 5) & (HD - 1);
    int ci = (t >> 13) % NCHUNK;
    int c  = (t >> 13) / NCHUNK;
    int l  = ci >> 3, q = ci & 7;
    float w = d_Wmid[(size_t)((c * NMID + l) * HD + r) * HD + q * KCH + k];
    __nv_bfloat16 hi = __float2bfloat16(w);
    __nv_bfloat16 lo = __float2bfloat16(w - __bfloat162float(hi));
    size_t base = (size_t)(c * NCHUNK + ci) * CHUNK_BYTES + (size_t)r * BROW + (size_t)k * 2;
    *reinterpret_cast<__nv_bfloat16*>(d_Wpk + base)           = hi;
    *reinterpret_cast<__nv_bfloat16*>(d_Wpk + base + CHUNK_B) = lo;
}

// ---------------- PTX helpers (base-target safe) ----------------
__device__ __forceinline__ void cp16(uint32_t s, const void* g) {
    asm volatile("cp.async.cg.shared.global [%0], [%1], 16;" :: "r"(s), "l"(g));
}
__device__ __forceinline__ void cp_commit()  { asm volatile("cp.async.commit_group;"); }
__device__ __forceinline__ void cp_wait1()   { asm volatile("cp.async.wait_group 1;" ::: "memory"); }
__device__ __forceinline__ void cp_wait0()   { asm volatile("cp.async.wait_group 0;" ::: "memory"); }

__device__ __forceinline__ void mma16816(float* d, const uint32_t* a, uint32_t b0, uint32_t b1) {
    asm volatile("mma.sync.aligned.m16n8k16.row.col.f32.bf16.bf16.f32 "
                 "{%0,%1,%2,%3}, {%4,%5,%6,%7}, {%8,%9}, {%0,%1,%2,%3};"
                 : "+f"(d[0]), "+f"(d[1]), "+f"(d[2]), "+f"(d[3])
                 : "r"(a[0]), "r"(a[1]), "r"(a[2]), "r"(a[3]), "r"(b0), "r"(b1));
}

__device__ __forceinline__ uint32_t pack_hi(float a, float b, float& ra, float& rb) {
    __nv_bfloat16 ah = __float2bfloat16(a);
    __nv_bfloat16 bh = __float2bfloat16(b);
    ra = a - __bfloat162float(ah);
    rb = b - __bfloat162float(bh);
    __nv_bfloat162 h2 = __halves2bfloat162(ah, bh);
    return *reinterpret_cast<uint32_t*>(&h2);
}
__device__ __forceinline__ uint32_t pack_lo(float ra, float rb) {
    __nv_bfloat162 l2 = __floats2bfloat162_rn(ra, rb);
    return *reinterpret_cast<uint32_t*>(&l2);
}

__device__ __forceinline__ uint32_t lds32(const unsigned char* smem, uint32_t off) {
    return *reinterpret_cast<const uint32_t*>(smem + off);
}

// ---------------- fused MLP: SIMT layer0 + HMMA mid layers ----------------
__global__ void __launch_bounds__(NTHR, 1)
mlpK(const float* __restrict__ X,
     const float* __restrict__ b_in,
     const float* __restrict__ b_mid,
     const float* __restrict__ b_out,
     float* __restrict__ out, int n) {
    extern __shared__ unsigned char smem[];

    int b = blockIdx.x;
    if (b >= d_blkoff[NC]) return;
    int c = 0;
    while (b >= d_blkoff[c + 1]) c++;
    int start = d_off[c] + (b - d_blkoff[c]) * TM;
    int cnt   = d_off[c + 1] - start;
    if (cnt > TM) cnt = TM;

    const int tid  = threadIdx.x;
    const int wid  = tid >> 5;
    const int lane = tid & 31;
    const int gid  = lane >> 2;
    const int tig  = lane & 3;
    const uint32_t sbase = (uint32_t)__cvta_generic_to_shared(smem);

    float* biasS = (float*)(smem + SM_BIAS);
    float* bInS  = (float*)(smem + SM_BIN);
    float* WoutS = (float*)(smem + SM_WOUT);
    float* boutS = (float*)(smem + SM_BOUT);
    int*   idxS  = (int*)  (smem + SM_IDX);
    float* WsS   = (float*)(smem + SM_WS);   // 256 x 37 fp32
    float* PS    = (float*)(smem + SM_P);    // 128 x 40 fp32

    // ---- stage: biases, Wout, b_in, layer0 weights ----
    for (int s = tid; s < NMID * HD; s += NTHR) {
        biasS[s] = b_mid[c * NMID * HD + s];
        WoutS[s] = d_Wout[c * NMID * HD + s];
    }
    for (int s = tid; s < HD; s += NTHR) bInS[s] = b_in[c * HD + s];
    if (tid < 3) boutS[tid] = b_out[c * NMID + tid];
    for (int s = tid; s < HD * DIN; s += NTHR) {
        int nn = s / DIN, kk = s - nn * DIN;
        WsS[nn * 37 + kk] = d_Win[(c * HD + nn) * DIN + kk];
    }

    // ---- posenc (fp32) into PS ----
    if (tid < TM) {
        const int m = tid;
        const int id = (m < cnt) ? d_sorted[start + m] : -1;
        idxS[m] = id;
        float* row = PS + m * 40;
        if (id >= 0) {
            float x = X[3 * id], y = X[3 * id + 1], z = X[3 * id + 2];
            float f = 1.f;
            #pragma unroll
            for (int fi = 0; fi < 6; fi++) {
                float s0, c0, s1, c1, s2, c2;
                sincosf(x * f, &s0, &c0);
                sincosf(y * f, &s1, &c1);
                sincosf(z * f, &s2, &c2);
                row[fi * 6 + 0] = s0; row[fi * 6 + 1] = s1; row[fi * 6 + 2] = s2;
                row[fi * 6 + 3] = c0; row[fi * 6 + 4] = c1; row[fi * 6 + 5] = c2;
                f *= 2.f;
            }
        } else {
            #pragma unroll
            for (int k = 0; k < DIN; k++) row[k] = 0.f;
        }
    }
    __syncthreads();

    // ---- layer 0: SIMT fp32 gemm ----
    {
        const int tx = tid & 15;    // 16 n-lanes
        const int ty = tid >> 4;    // 32 m-groups of 4
        float acc[4][16];
        #pragma unroll
        for (int i = 0; i < 4; i++)
            #pragma unroll
            for (int j = 0; j < 16; j++) acc[i][j] = 0.f;

        #pragma unroll 4
        for (int kk = 0; kk < DIN; kk++) {
            float a0 = PS[(ty * 4 + 0) * 40 + kk];
            float a1 = PS[(ty * 4 + 1) * 40 + kk];
            float a2 = PS[(ty * 4 + 2) * 40 + kk];
            float a3 = PS[(ty * 4 + 3) * 40 + kk];
            #pragma unroll
            for (int jj = 0; jj < 16; jj++) {
                float w = WsS[(tx + 16 * jj) * 37 + kk];
                acc[0][jj] = fmaf(a0, w, acc[0][jj]);
                acc[1][jj] = fmaf(a1, w, acc[1][jj]);
                acc[2][jj] = fmaf(a2, w, acc[2][jj]);
                acc[3][jj] = fmaf(a3, w, acc[3][jj]);
            }
        }
        __syncthreads();   // done reading PS/WsS (region reused by cp.async below)

        // bias + relu + split -> A hi/lo bf16 images
        #pragma unroll
        for (int jj = 0; jj < 16; jj++) {
            int nn = tx + 16 * jj;
            float bb = bInS[nn];
            #pragma unroll
            for (int ii = 0; ii < 4; ii++) {
                int m = ty * 4 + ii;
                float v = fmaxf(acc[ii][jj] + bb, 0.f);
                __nv_bfloat16 hi = __float2bfloat16(v);
                __nv_bfloat16 lo = __float2bfloat16(v - __bfloat162float(hi));
                *reinterpret_cast<__nv_bfloat16*>(smem + SM_AHI + m * AROW + nn * 2) = hi;
                *reinterpret_cast<__nv_bfloat16*>(smem + SM_ALO + m * AROW + nn * 2) = lo;
            }
        }
    }
    __syncthreads();

    // ---- mid layers: HMMA ----
    const int m_base = (wid & 3) * 32;
    const int n_base = (wid >> 2) * 64;
    const uint32_t a_row0 = (uint32_t)(m_base + gid) * AROW + (uint32_t)tig * 4;
    const uint32_t b_row0 = (uint32_t)(n_base + gid) * BROW + (uint32_t)tig * 4;

    const unsigned char* wsrc = d_Wpk + (size_t)c * NCHUNK * CHUNK_BYTES;

    // prefetch chunk 0 into buffer 0
    {
        const unsigned char* g = wsrc;
        #pragma unroll
        for (int j = 0; j < 5; j++) {
            int o = (tid + j * NTHR) * 16;
            cp16(sbase + SM_B + o, g + o);
        }
        cp_commit();
    }

    int q = 0;

    #pragma unroll 1
    for (int l = 0; l < 3; l++) {
        float D[2][8][4];
        #pragma unroll
        for (int im = 0; im < 2; im++)
            #pragma unroll
            for (int jn = 0; jn < 8; jn++)
                #pragma unroll
                for (int e = 0; e < 4; e++) D[im][jn][e] = 0.f;

        #pragma unroll 1
        for (int i = 0; i < 8; i++) {
            bool pf = (q + 1 < NCHUNK);
            if (pf) {
                const unsigned char* g = wsrc + (size_t)(q + 1) * CHUNK_BYTES;
                uint32_t sb = sbase + SM_B + ((q + 1) & 1) * CHUNK_BYTES;
                #pragma unroll
                for (int j = 0; j < 5; j++) {
                    int o = (tid + j * NTHR) * 16;
                    cp16(sb + o, g + o);
                }
                cp_commit();
                cp_wait1();
            } else {
                cp_wait0();
            }
            __syncthreads();

            const unsigned char* bbuf   = smem + SM_B + (q & 1) * CHUNK_BYTES;
            const unsigned char* bbufLo = bbuf + CHUNK_B;
            const uint32_t kA = (uint32_t)(i * KCH) * 2;

            #pragma unroll
            for (int ks = 0; ks < 2; ks++) {
                const uint32_t kbA = kA + (uint32_t)ks * 32;
                const uint32_t kbB = (uint32_t)ks * 32;

                uint32_t Ahi[2][4], Alo[2][4];
                #pragma unroll
                for (int im = 0; im < 2; im++) {
                    uint32_t r0 = a_row0 + (uint32_t)(im * 16) * AROW + kbA;
                    uint32_t r1 = r0 + 8u * AROW;
                    Ahi[im][0] = lds32(smem, SM_AHI + r0);
                    Ahi[im][1] = lds32(smem, SM_AHI + r1);
                    Ahi[im][2] = lds32(smem, SM_AHI + r0 + 16);
                    Ahi[im][3] = lds32(smem, SM_AHI + r1 + 16);
                    Alo[im][0] = lds32(smem, SM_ALO + r0);
                    Alo[im][1] = lds32(smem, SM_ALO + r1);
                    Alo[im][2] = lds32(smem, SM_ALO + r0 + 16);
                    Alo[im][3] = lds32(smem, SM_ALO + r1 + 16);
                }

                #pragma unroll
                for (int jg = 0; jg < 4; jg++) {
                    uint32_t o0 = b_row0 + (uint32_t)(jg * 16) * BROW + kbB;
                    uint32_t o1 = o0 + 8u * BROW;
                    uint32_t bh0 = *(const uint32_t*)(bbuf   + o0);
                    uint32_t bh1 = *(const uint32_t*)(bbuf   + o0 + 16);
                    uint32_t bh2 = *(const uint32_t*)(bbuf   + o1);
                    uint32_t bh3 = *(const uint32_t*)(bbuf   + o1 + 16);
                    uint32_t bl0 = *(const uint32_t*)(bbufLo + o0);
                    uint32_t bl1 = *(const uint32_t*)(bbufLo + o0 + 16);
                    uint32_t bl2 = *(const uint32_t*)(bbufLo + o1);
                    uint32_t bl3 = *(const uint32_t*)(bbufLo + o1 + 16);
                    #pragma unroll
                    for (int im = 0; im < 2; im++) {
                        mma16816(D[im][jg * 2],     Ahi[im], bh0, bh1);
                        mma16816(D[im][jg * 2 + 1], Ahi[im], bh2, bh3);
                        mma16816(D[im][jg * 2],     Ahi[im], bl0, bl1);
                        mma16816(D[im][jg * 2 + 1], Ahi[im], bl2, bl3);
                        mma16816(D[im][jg * 2],     Alo[im], bh0, bh1);
                        mma16816(D[im][jg * 2 + 1], Alo[im], bh2, bh3);
                    }
                }
            }
            __syncthreads();
            q++;
        }

        // ---- epilogue ----
        const float* bias = biasS + l * HD;
        if (l < 2) {
            #pragma unroll
            for (int im = 0; im < 2; im++) {
                #pragma unroll
                for (int jn = 0; jn < 8; jn++) {
                    int ncol = n_base + jn * 8 + tig * 2;
                    float b0 = bias[ncol], b1 = bias[ncol + 1];
                    #pragma unroll
                    for (int h = 0; h < 2; h++) {
                        int m = m_base + im * 16 + gid + h * 8;
                        float v0 = fmaxf(D[im][jn][2 * h]     + b0, 0.f);
                        float v1 = fmaxf(D[im][jn][2 * h + 1] + b1, 0.f);
                        float ra, rb;
                        uint32_t ph = pack_hi(v0, v1, ra, rb);
                        uint32_t pl = pack_lo(ra, rb);
                        *(uint32_t*)(smem + SM_AHI + m * AROW + ncol * 2) = ph;
                        *(uint32_t*)(smem + SM_ALO + m * AROW + ncol * 2) = pl;
                    }
                }
            }
            __syncthreads();
        } else {
            // final hidden -> fp32 h in A region, row stride HROW=264 floats
            // (128 * 264 * 4 = 135168 bytes = exactly the A-hi + A-lo region, dead now)
            float* hbuf = (float*)(smem + SM_AHI);
            #pragma unroll
            for (int im = 0; im < 2; im++) {
                #pragma unroll
                for (int jn = 0; jn < 8; jn++) {
                    int ncol = n_base + jn * 8 + tig * 2;
                    float b0 = bias[ncol], b1 = bias[ncol + 1];
                    #pragma unroll
                    for (int h = 0; h < 2; h++) {
                        int m = m_base + im * 16 + gid + h * 8;
                        float v0 = fmaxf(D[im][jn][2 * h]     + b0, 0.f);
                        float v1 = fmaxf(D[im][jn][2 * h + 1] + b1, 0.f);
                        float2* p = (float2*)(hbuf + m * HROW + ncol);
                        *p = make_float2(v0, v1);
                    }
                }
            }
            __syncthreads();
            // fused output layer: 384 (m,j) dots of length 256
            const float* hb = (const float*)(smem + SM_AHI);
            #pragma unroll
            for (int qq = 0; qq < 24; qq++) {
                int o = wid * 24 + qq;
                int m = o / 3, j = o - 3 * m;
                const float* hr = hb + m * HROW;
                const float* wr = WoutS + j * HD;
                float s = 0.f;
                #pragma unroll
                for (int k = lane; k < HD; k += 32) s = fmaf(hr[k], wr[k], s);
                #pragma unroll
                for (int off = 16; off; off >>= 1) s += __shfl_xor_sync(0xffffffffu, s, off);
                if (lane == 0) {
                    int id = idxS[m];
                    if (id >= 0) out[3 * id + j] = tanhf(s + boutS[j]);
                }
            }
        }
    }
}

// ---------------- launch ----------------
extern "C" void kernel_launch(void* const* d_in, const int* in_sizes, int n_in,
                              void* d_out, int out_size) {
    const float* X     = (const float*)d_in[0];
    const int*   cid   = (const int*)  d_in[1];
    const float* V_in  = (const float*)d_in[2];
    const float* g_in  = (const float*)d_in[3];
    const float* b_in  = (const float*)d_in[4];
    const float* V_mid = (const float*)d_in[5];
    const float* g_mid = (const float*)d_in[6];
    const float* b_mid = (const float*)d_in[7];
    const float* V_out = (const float*)d_in[8];
    const float* g_out = (const float*)d_in[9];
    const float* b_out = (const float*)d_in[10];
    float* out = (float*)d_out;
    const int n = in_sizes[0] / 3;

    cudaFuncSetAttribute(mlpK, cudaFuncAttributeMaxDynamicSharedMemorySize, SMEM_BYTES);

    initK<<<1, 32>>>();
    histK<<<256, 256>>>(cid, n);
    prefixK<<<1, 1>>>();
    scatterK<<<(n + 255) / 256, 256>>>(cid, n);

    normWinK <<<(NC * HD        + 7) / 8, 256>>>(V_in,  g_in);
    normWmidK<<<(NC * NMID * HD + 7) / 8, 256>>>(V_mid, g_mid);
    normWoutK<<<(NC * NMID      + 7) / 8, 256>>>(V_out, g_out);

    const int packTotal = NC * NCHUNK * HD * KCH;
    packK<<<(packTotal + 255) / 256, 256>>>();

    const int blocks = (n + TM - 1) / TM + NC;
    mlpK<<<blocks, NTHR, SMEM_BYTES>>>(X, b_in, b_mid, b_out, out, n);
}

// round 7
// speedup vs baseline: 3.9463x; 1.5821x over previous
#include <cuda_runtime.h>
#include <cuda_bf16.h>
#include <math.h>
#include <stdint.h>

// ---------------- problem constants ----------------
#define NC    8
#define HD    256
#define DIN   36
#define NMID  3
#define NMAX  65536
#define TM    128          // points per CTA
#define NTHR  512          // 16 warps: 4 (m) x 4 (n)

#define KCH       32       // K chunk
#define NCHUNK    24       // 3 mid layers x 8 chunks
#define BROW      80       // B SMEM row stride bytes (20 words -> conflict-free)
#define CHUNK_B   (HD * BROW)          // 20480 per split
#define CHUNK_BYTES (2 * CHUNK_B)      // hi + lo = 40960
#define AROW      528      // A SMEM row stride bytes (132 words -> conflict-free)
#define HROW      264      // final fp32 hidden row stride (floats)

// SMEM layout (bytes)
#define SM_AHI   0
#define SM_ALO   (SM_AHI + TM * AROW)            // 67584
#define SM_B     (SM_ALO + TM * AROW)            // 135168  (2 x 40960)
#define SM_WS    SM_B                            // overlay: Win slice 256x37 fp32
#define SM_P     (SM_B + 256 * 37 * 4)           // overlay: posenc 128x40 fp32
#define SM_BIAS  (SM_B + 2 * CHUNK_BYTES)        // 217088  (3*256 floats, mid biases)
#define SM_BIN   (SM_BIAS + NMID * HD * 4)       // 220160
#define SM_WOUT  (SM_BIN + HD * 4)               // 221184
#define SM_BOUT  (SM_WOUT + 3 * HD * 4)          // 224256
#define SM_IDX   (SM_BOUT + 16)                  // 224272
#define SMEM_BYTES (SM_IDX + TM * 4)             // 224784

// prep kernel block ranges
#define NB_SCAT  256
#define NB_MID   768      // 6144 mid rows / 8 warps
#define NB_WIN   256      // 2048 win rows / 8 warps
#define NB_WOUT  1
#define NB_PREP  (NB_SCAT + NB_MID + NB_WIN + NB_WOUT)

// ---------------- device scratch ----------------
__device__ float d_Win [NC * HD * DIN];          // normalized layer0 weights
__device__ float d_Wout[NC * NMID * HD];         // normalized output weights
__device__ __align__(128) unsigned char d_Wpk[NC * NCHUNK * CHUNK_BYTES];
__device__ int   d_sortedPad[NC * NMAX];         // padded per-cluster index regions
__device__ int   d_cursor[NC];                   // per-cluster counts
__device__ int   d_blkoff[NC + 1];

// ---------------- setup kernels ----------------
__global__ void initK() { if (threadIdx.x < NC) d_cursor[threadIdx.x] = 0; }

// fused prep: scatter + weight-norm + split-pack
__global__ void prepK(const int* __restrict__ cid, int n,
                      const float* __restrict__ V_in,  const float* __restrict__ g_in,
                      const float* __restrict__ V_mid, const float* __restrict__ g_mid,
                      const float* __restrict__ V_out, const float* __restrict__ g_out) {
    const int blk  = blockIdx.x;
    const int tid  = threadIdx.x;
    const int wid  = tid >> 5;
    const int lane = tid & 31;

    if (blk < NB_SCAT) {
        // ---- scatter into padded per-cluster regions ----
        __shared__ int lh[NC], base[NC];
        if (tid < NC) lh[tid] = 0;
        __syncthreads();
        int i = blk * 256 + tid;
        int c = -1, r = 0;
        if (i < n) { c = cid[i]; r = atomicAdd(&lh[c], 1); }
        __syncthreads();
        if (tid < NC) base[tid] = atomicAdd(&d_cursor[tid], lh[tid]);
        __syncthreads();
        if (i < n) d_sortedPad[c * NMAX + base[c] + r] = i;
        return;
    }
    if (blk < NB_SCAT + NB_MID) {
        // ---- mid weights: norm + split-bf16 pack (one warp per row) ----
        int row = (blk - NB_SCAT) * 8 + wid;         // [0, 6144)
        int c = row / (NMID * HD);
        int l = (row / HD) % NMID;
        int r = row & (HD - 1);
        const float* v = V_mid + (size_t)row * HD;
        float vals[8];
        float s = 0.f;
        #pragma unroll
        for (int j = 0; j < 8; j++) { vals[j] = v[lane + 32 * j]; s = fmaf(vals[j], vals[j], s); }
        #pragma unroll
        for (int off = 16; off; off >>= 1) s += __shfl_xor_sync(0xffffffffu, s, off);
        float scale = g_mid[row] * rsqrtf(s);
        #pragma unroll
        for (int j = 0; j < 8; j++) {
            float w = vals[j] * scale;
            __nv_bfloat16 hi = __float2bfloat16(w);
            __nv_bfloat16 lo = __float2bfloat16(w - __bfloat162float(hi));
            int ci = l * 8 + j;
            size_t base = (size_t)(c * NCHUNK + ci) * CHUNK_BYTES + (size_t)r * BROW + (size_t)lane * 2;
            *reinterpret_cast<__nv_bfloat16*>(d_Wpk + base)           = hi;
            *reinterpret_cast<__nv_bfloat16*>(d_Wpk + base + CHUNK_B) = lo;
        }
        return;
    }
    if (blk < NB_SCAT + NB_MID + NB_WIN) {
        // ---- layer-0 weights: norm only (one warp per row) ----
        int row = (blk - NB_SCAT - NB_MID) * 8 + wid;   // [0, 2048)
        const float* v = V_in + (size_t)row * DIN;
        float v0 = v[lane];
        float v1 = (lane < DIN - 32) ? v[32 + lane] : 0.f;
        float s = fmaf(v0, v0, v1 * v1);
        #pragma unroll
        for (int off = 16; off; off >>= 1) s += __shfl_xor_sync(0xffffffffu, s, off);
        float scale = g_in[row] * rsqrtf(s);
        d_Win[row * DIN + lane] = v0 * scale;
        if (lane < DIN - 32) d_Win[row * DIN + 32 + lane] = v1 * scale;
        return;
    }
    // ---- output weights: norm only (8 warps x 3 rows = 24 rows) ----
    {
        #pragma unroll
        for (int it = 0; it < 3; it++) {
            int row = wid * 3 + it;                    // [0, 24)
            const float* v = V_out + (size_t)row * HD;
            float vals[8];
            float s = 0.f;
            #pragma unroll
            for (int j = 0; j < 8; j++) { vals[j] = v[lane + 32 * j]; s = fmaf(vals[j], vals[j], s); }
            #pragma unroll
            for (int off = 16; off; off >>= 1) s += __shfl_xor_sync(0xffffffffu, s, off);
            float scale = g_out[row] * rsqrtf(s);
            #pragma unroll
            for (int j = 0; j < 8; j++) d_Wout[row * HD + lane + 32 * j] = vals[j] * scale;
        }
    }
}

__global__ void prefixK() {
    if (threadIdx.x == 0) {
        int bo = 0;
        for (int c = 0; c < NC; c++) {
            d_blkoff[c] = bo;
            bo += (d_cursor[c] + TM - 1) / TM;
        }
        d_blkoff[NC] = bo;
    }
}

// ---------------- PTX helpers ----------------
__device__ __forceinline__ void cp16(uint32_t s, const void* g) {
    asm volatile("cp.async.cg.shared.global [%0], [%1], 16;" :: "r"(s), "l"(g));
}
__device__ __forceinline__ void cp_commit()  { asm volatile("cp.async.commit_group;"); }
__device__ __forceinline__ void cp_wait1()   { asm volatile("cp.async.wait_group 1;" ::: "memory"); }
__device__ __forceinline__ void cp_wait0()   { asm volatile("cp.async.wait_group 0;" ::: "memory"); }

__device__ __forceinline__ void mma16816(float* d, const uint32_t* a, uint32_t b0, uint32_t b1) {
    asm volatile("mma.sync.aligned.m16n8k16.row.col.f32.bf16.bf16.f32 "
                 "{%0,%1,%2,%3}, {%4,%5,%6,%7}, {%8,%9}, {%0,%1,%2,%3};"
                 : "+f"(d[0]), "+f"(d[1]), "+f"(d[2]), "+f"(d[3])
                 : "r"(a[0]), "r"(a[1]), "r"(a[2]), "r"(a[3]), "r"(b0), "r"(b1));
}

__device__ __forceinline__ uint32_t pack_hi(float a, float b, float& ra, float& rb) {
    __nv_bfloat16 ah = __float2bfloat16(a);
    __nv_bfloat16 bh = __float2bfloat16(b);
    ra = a - __bfloat162float(ah);
    rb = b - __bfloat162float(bh);
    __nv_bfloat162 h2 = __halves2bfloat162(ah, bh);
    return *reinterpret_cast<uint32_t*>(&h2);
}
__device__ __forceinline__ uint32_t pack_lo(float ra, float rb) {
    __nv_bfloat162 l2 = __floats2bfloat162_rn(ra, rb);
    return *reinterpret_cast<uint32_t*>(&l2);
}

__device__ __forceinline__ uint32_t lds32(const unsigned char* smem, uint32_t off) {
    return *reinterpret_cast<const uint32_t*>(smem + off);
}

// ---------------- fused MLP: SIMT layer0 + HMMA mid layers ----------------
__global__ void __launch_bounds__(NTHR, 1)
mlpK(const float* __restrict__ X,
     const float* __restrict__ b_in,
     const float* __restrict__ b_mid,
     const float* __restrict__ b_out,
     float* __restrict__ out, int n) {
    extern __shared__ unsigned char smem[];

    int b = blockIdx.x;
    if (b >= d_blkoff[NC]) return;
    int c = 0;
    while (b >= d_blkoff[c + 1]) c++;
    const int tile  = b - d_blkoff[c];
    const int start = tile * TM;
    int cnt = d_cursor[c] - start;
    if (cnt > TM) cnt = TM;
    if (cnt < 0) cnt = 0;

    const int tid  = threadIdx.x;
    const int wid  = tid >> 5;
    const int lane = tid & 31;
    const int gid  = lane >> 2;
    const int tig  = lane & 3;
    const uint32_t sbase = (uint32_t)__cvta_generic_to_shared(smem);

    float* biasS = (float*)(smem + SM_BIAS);
    float* bInS  = (float*)(smem + SM_BIN);
    float* WoutS = (float*)(smem + SM_WOUT);
    float* boutS = (float*)(smem + SM_BOUT);
    int*   idxS  = (int*)  (smem + SM_IDX);
    float* WsS   = (float*)(smem + SM_WS);   // 256 x 37 fp32
    float* PS    = (float*)(smem + SM_P);    // 128 x 40 fp32

    // ---- stage: biases, Wout, b_in, layer0 weights ----
    for (int s = tid; s < NMID * HD; s += NTHR) {
        biasS[s] = b_mid[c * NMID * HD + s];
        WoutS[s] = d_Wout[c * NMID * HD + s];
    }
    for (int s = tid; s < HD; s += NTHR) bInS[s] = b_in[c * HD + s];
    if (tid < 3) boutS[tid] = b_out[c * NMID + tid];
    for (int s = tid; s < HD * DIN; s += NTHR) {
        int nn = s / DIN, kk = s - nn * DIN;
        WsS[nn * 37 + kk] = d_Win[(c * HD + nn) * DIN + kk];
    }

    // ---- posenc (fp32) into PS ----
    if (tid < TM) {
        const int m = tid;
        const int id = (m < cnt) ? d_sortedPad[c * NMAX + start + m] : -1;
        idxS[m] = id;
        float* row = PS + m * 40;
        if (id >= 0) {
            float x = X[3 * id], y = X[3 * id + 1], z = X[3 * id + 2];
            float f = 1.f;
            #pragma unroll
            for (int fi = 0; fi < 6; fi++) {
                float s0, c0, s1, c1, s2, c2;
                sincosf(x * f, &s0, &c0);
                sincosf(y * f, &s1, &c1);
                sincosf(z * f, &s2, &c2);
                row[fi * 6 + 0] = s0; row[fi * 6 + 1] = s1; row[fi * 6 + 2] = s2;
                row[fi * 6 + 3] = c0; row[fi * 6 + 4] = c1; row[fi * 6 + 5] = c2;
                f *= 2.f;
            }
        } else {
            #pragma unroll
            for (int k = 0; k < DIN; k++) row[k] = 0.f;
        }
    }
    __syncthreads();

    // ---- layer 0: SIMT fp32 gemm ----
    {
        const int tx = tid & 15;
        const int ty = tid >> 4;
        float acc[4][16];
        #pragma unroll
        for (int i = 0; i < 4; i++)
            #pragma unroll
            for (int j = 0; j < 16; j++) acc[i][j] = 0.f;

        #pragma unroll 4
        for (int kk = 0; kk < DIN; kk++) {
            float a0 = PS[(ty * 4 + 0) * 40 + kk];
            float a1 = PS[(ty * 4 + 1) * 40 + kk];
            float a2 = PS[(ty * 4 + 2) * 40 + kk];
            float a3 = PS[(ty * 4 + 3) * 40 + kk];
            #pragma unroll
            for (int jj = 0; jj < 16; jj++) {
                float w = WsS[(tx + 16 * jj) * 37 + kk];
                acc[0][jj] = fmaf(a0, w, acc[0][jj]);
                acc[1][jj] = fmaf(a1, w, acc[1][jj]);
                acc[2][jj] = fmaf(a2, w, acc[2][jj]);
                acc[3][jj] = fmaf(a3, w, acc[3][jj]);
            }
        }
        __syncthreads();   // done reading PS/WsS (region reused by cp.async below)

        #pragma unroll
        for (int jj = 0; jj < 16; jj++) {
            int nn = tx + 16 * jj;
            float bb = bInS[nn];
            #pragma unroll
            for (int ii = 0; ii < 4; ii++) {
                int m = ty * 4 + ii;
                float v = fmaxf(acc[ii][jj] + bb, 0.f);
                __nv_bfloat16 hi = __float2bfloat16(v);
                __nv_bfloat16 lo = __float2bfloat16(v - __bfloat162float(hi));
                *reinterpret_cast<__nv_bfloat16*>(smem + SM_AHI + m * AROW + nn * 2) = hi;
                *reinterpret_cast<__nv_bfloat16*>(smem + SM_ALO + m * AROW + nn * 2) = lo;
            }
        }
    }
    __syncthreads();

    // ---- mid layers: HMMA ----
    const int m_base = (wid & 3) * 32;
    const int n_base = (wid >> 2) * 64;
    const uint32_t a_row0 = (uint32_t)(m_base + gid) * AROW + (uint32_t)tig * 4;
    const uint32_t b_row0 = (uint32_t)(n_base + gid) * BROW + (uint32_t)tig * 4;

    const unsigned char* wsrc = d_Wpk + (size_t)c * NCHUNK * CHUNK_BYTES;

    // prefetch chunk 0 into buffer 0
    {
        const unsigned char* g = wsrc;
        #pragma unroll
        for (int j = 0; j < 5; j++) {
            int o = (tid + j * NTHR) * 16;
            cp16(sbase + SM_B + o, g + o);
        }
        cp_commit();
    }

    int q = 0;

    #pragma unroll 1
    for (int l = 0; l < 3; l++) {
        float D[2][8][4];
        #pragma unroll
        for (int im = 0; im < 2; im++)
            #pragma unroll
            for (int jn = 0; jn < 8; jn++)
                #pragma unroll
                for (int e = 0; e < 4; e++) D[im][jn][e] = 0.f;

        #pragma unroll 1
        for (int i = 0; i < 8; i++) {
            bool pf = (q + 1 < NCHUNK);
            if (pf) {
                const unsigned char* g = wsrc + (size_t)(q + 1) * CHUNK_BYTES;
                uint32_t sb = sbase + SM_B + ((q + 1) & 1) * CHUNK_BYTES;
                #pragma unroll
                for (int j = 0; j < 5; j++) {
                    int o = (tid + j * NTHR) * 16;
                    cp16(sb + o, g + o);
                }
                cp_commit();
                cp_wait1();
            } else {
                cp_wait0();
            }
            __syncthreads();

            const unsigned char* bbuf   = smem + SM_B + (q & 1) * CHUNK_BYTES;
            const unsigned char* bbufLo = bbuf + CHUNK_B;
            const uint32_t kA = (uint32_t)(i * KCH) * 2;

            #pragma unroll
            for (int ks = 0; ks < 2; ks++) {
                const uint32_t kbA = kA + (uint32_t)ks * 32;
                const uint32_t kbB = (uint32_t)ks * 32;

                // ---- load A fragments (hi + lo) ----
                uint32_t Ahi[2][4], Alo[2][4];
                #pragma unroll
                for (int im = 0; im < 2; im++) {
                    uint32_t r0 = a_row0 + (uint32_t)(im * 16) * AROW + kbA;
                    uint32_t r1 = r0 + 8u * AROW;
                    Ahi[im][0] = lds32(smem, SM_AHI + r0);
                    Ahi[im][1] = lds32(smem, SM_AHI + r1);
                    Ahi[im][2] = lds32(smem, SM_AHI + r0 + 16);
                    Ahi[im][3] = lds32(smem, SM_AHI + r1 + 16);
                    Alo[im][0] = lds32(smem, SM_ALO + r0);
                    Alo[im][1] = lds32(smem, SM_ALO + r1);
                    Alo[im][2] = lds32(smem, SM_ALO + r0 + 16);
                    Alo[im][3] = lds32(smem, SM_ALO + r1 + 16);
                }

                // ---- load B-hi fragments for all 4 jg ----
                uint32_t Bf[4][4];
                #pragma unroll
                for (int jg = 0; jg < 4; jg++) {
                    uint32_t o0 = b_row0 + (uint32_t)(jg * 16) * BROW + kbB;
                    uint32_t o1 = o0 + 8u * BROW;
                    Bf[jg][0] = *(const uint32_t*)(bbuf + o0);
                    Bf[jg][1] = *(const uint32_t*)(bbuf + o0 + 16);
                    Bf[jg][2] = *(const uint32_t*)(bbuf + o1);
                    Bf[jg][3] = *(const uint32_t*)(bbuf + o1 + 16);
                }

                // ---- split-major MMA issue: same-D writes 16 apart ----
                // s0: Ahi x Bhi
                #pragma unroll
                for (int jg = 0; jg < 4; jg++)
                    #pragma unroll
                    for (int im = 0; im < 2; im++) {
                        mma16816(D[im][jg * 2],     Ahi[im], Bf[jg][0], Bf[jg][1]);
                        mma16816(D[im][jg * 2 + 1], Ahi[im], Bf[jg][2], Bf[jg][3]);
                    }
                // s1: Alo x Bhi
                #pragma unroll
                for (int jg = 0; jg < 4; jg++)
                    #pragma unroll
                    for (int im = 0; im < 2; im++) {
                        mma16816(D[im][jg * 2],     Alo[im], Bf[jg][0], Bf[jg][1]);
                        mma16816(D[im][jg * 2 + 1], Alo[im], Bf[jg][2], Bf[jg][3]);
                    }
                // ---- load B-lo fragments (reuse regs) ----
                #pragma unroll
                for (int jg = 0; jg < 4; jg++) {
                    uint32_t o0 = b_row0 + (uint32_t)(jg * 16) * BROW + kbB;
                    uint32_t o1 = o0 + 8u * BROW;
                    Bf[jg][0] = *(const uint32_t*)(bbufLo + o0);
                    Bf[jg][1] = *(const uint32_t*)(bbufLo + o0 + 16);
                    Bf[jg][2] = *(const uint32_t*)(bbufLo + o1);
                    Bf[jg][3] = *(const uint32_t*)(bbufLo + o1 + 16);
                }
                // s2: Ahi x Blo
                #pragma unroll
                for (int jg = 0; jg < 4; jg++)
                    #pragma unroll
                    for (int im = 0; im < 2; im++) {
                        mma16816(D[im][jg * 2],     Ahi[im], Bf[jg][0], Bf[jg][1]);
                        mma16816(D[im][jg * 2 + 1], Ahi[im], Bf[jg][2], Bf[jg][3]);
                    }
            }
            __syncthreads();
            q++;
        }

        // ---- epilogue ----
        const float* bias = biasS + l * HD;
        if (l < 2) {
            #pragma unroll
            for (int im = 0; im < 2; im++) {
                #pragma unroll
                for (int jn = 0; jn < 8; jn++) {
                    int ncol = n_base + jn * 8 + tig * 2;
                    float b0 = bias[ncol], b1 = bias[ncol + 1];
                    #pragma unroll
                    for (int h = 0; h < 2; h++) {
                        int m = m_base + im * 16 + gid + h * 8;
                        float v0 = fmaxf(D[im][jn][2 * h]     + b0, 0.f);
                        float v1 = fmaxf(D[im][jn][2 * h + 1] + b1, 0.f);
                        float ra, rb;
                        uint32_t ph = pack_hi(v0, v1, ra, rb);
                        uint32_t pl = pack_lo(ra, rb);
                        *(uint32_t*)(smem + SM_AHI + m * AROW + ncol * 2) = ph;
                        *(uint32_t*)(smem + SM_ALO + m * AROW + ncol * 2) = pl;
                    }
                }
            }
            __syncthreads();
        } else {
            // final hidden -> fp32 h, row stride HROW=264 floats (fits A region)
            float* hbuf = (float*)(smem + SM_AHI);
            #pragma unroll
            for (int im = 0; im < 2; im++) {
                #pragma unroll
                for (int jn = 0; jn < 8; jn++) {
                    int ncol = n_base + jn * 8 + tig * 2;
                    float b0 = bias[ncol], b1 = bias[ncol + 1];
                    #pragma unroll
                    for (int h = 0; h < 2; h++) {
                        int m = m_base + im * 16 + gid + h * 8;
                        float v0 = fmaxf(D[im][jn][2 * h]     + b0, 0.f);
                        float v1 = fmaxf(D[im][jn][2 * h + 1] + b1, 0.f);
                        float2* p = (float2*)(hbuf + m * HROW + ncol);
                        *p = make_float2(v0, v1);
                    }
                }
            }
            __syncthreads();
            // fused output layer: 384 (m,j) dots of length 256
            const float* hb = (const float*)(smem + SM_AHI);
            #pragma unroll
            for (int qq = 0; qq < 24; qq++) {
                int o = wid * 24 + qq;
                int m = o / 3, j = o - 3 * m;
                const float* hr = hb + m * HROW;
                const float* wr = WoutS + j * HD;
                float s = 0.f;
                #pragma unroll
                for (int k = lane; k < HD; k += 32) s = fmaf(hr[k], wr[k], s);
                #pragma unroll
                for (int off = 16; off; off >>= 1) s += __shfl_xor_sync(0xffffffffu, s, off);
                if (lane == 0) {
                    int id = idxS[m];
                    if (id >= 0) out[3 * id + j] = tanhf(s + boutS[j]);
                }
            }
        }
    }
}

// ---------------- launch ----------------
extern "C" void kernel_launch(void* const* d_in, const int* in_sizes, int n_in,
                              void* d_out, int out_size) {
    const float* X     = (const float*)d_in[0];
    const int*   cid   = (const int*)  d_in[1];
    const float* V_in  = (const float*)d_in[2];
    const float* g_in  = (const float*)d_in[3];
    const float* b_in  = (const float*)d_in[4];
    const float* V_mid = (const float*)d_in[5];
    const float* g_mid = (const float*)d_in[6];
    const float* b_mid = (const float*)d_in[7];
    const float* V_out = (const float*)d_in[8];
    const float* g_out = (const float*)d_in[9];
    const float* b_out = (const float*)d_in[10];
    float* out = (float*)d_out;
    const int n = in_sizes[0] / 3;

    cudaFuncSetAttribute(mlpK, cudaFuncAttributeMaxDynamicSharedMemorySize, SMEM_BYTES);

    initK<<<1, 32>>>();
    prepK<<<NB_PREP, 256>>>(cid, n, V_in, g_in, V_mid, g_mid, V_out, g_out);
    prefixK<<<1, 1>>>();

    const int blocks = (n + TM - 1) / TM + NC;
    mlpK<<<blocks, NTHR, SMEM_BYTES>>>(X, b_in, b_mid, b_out, out, n);
}

// round 8
// speedup vs baseline: 4.0204x; 1.0188x over previous
#include <cuda_runtime.h>
#include <cuda_bf16.h>
#include <math.h>
#include <stdint.h>

// ---------------- problem constants ----------------
#define NC    8
#define HD    256
#define DIN   36
#define NMID  3
#define NMAX  65536
#define TM    128          // points per CTA
#define NTHR  512          // 16 warps: 4 (m) x 4 (n)

#define KCH       32       // K chunk
#define NCHUNK    24       // 3 mid layers x 8 chunks
#define BROW      80       // B SMEM row stride bytes (20 words -> conflict-free)
#define CHUNK_B   (HD * BROW)          // 20480 per split
#define CHUNK_BYTES (2 * CHUNK_B)      // hi + lo = 40960
#define AROW      528      // A SMEM row stride bytes (132 words -> conflict-free)
#define HROW      264      // final fp32 hidden row stride (floats)

// SMEM layout (bytes)
#define SM_AHI   0
#define SM_ALO   (SM_AHI + TM * AROW)            // 67584
#define SM_B     (SM_ALO + TM * AROW)            // 135168  (2 x 40960)
#define SM_WS    SM_B                            // overlay: Win slice 256x37 fp32
#define SM_P     (SM_B + 256 * 37 * 4)           // overlay: posenc 128x40 fp32
#define SM_BIAS  (SM_B + 2 * CHUNK_BYTES)        // 217088  (3*256 floats, mid biases)
#define SM_BIN   (SM_BIAS + NMID * HD * 4)       // 220160
#define SM_WOUT  (SM_BIN + HD * 4)               // 221184
#define SM_BOUT  (SM_WOUT + 3 * HD * 4)          // 224256
#define SM_IDX   (SM_BOUT + 16)                  // 224272
#define SMEM_BYTES (SM_IDX + TM * 4)             // 224784

// prep kernel block ranges
#define NB_SCAT  256
#define NB_MID   768      // 6144 mid rows / 8 warps
#define NB_WIN   256      // 2048 win rows / 8 warps
#define NB_WOUT  1
#define NB_PREP  (NB_SCAT + NB_MID + NB_WIN + NB_WOUT)

// ---------------- device scratch ----------------
__device__ float d_Win [NC * HD * DIN];          // normalized layer0 weights
__device__ float d_Wout[NC * NMID * HD];         // normalized output weights
__device__ __align__(128) unsigned char d_Wpk[NC * NCHUNK * CHUNK_BYTES];
__device__ int   d_sortedPad[NC * NMAX];         // padded per-cluster index regions
__device__ int   d_cursor[NC];                   // per-cluster counts
__device__ int   d_blkoff[NC + 1];

// ---------------- setup kernels ----------------
__global__ void initK() { if (threadIdx.x < NC) d_cursor[threadIdx.x] = 0; }

// fused prep: scatter + weight-norm + split-pack
__global__ void prepK(const int* __restrict__ cid, int n,
                      const float* __restrict__ V_in,  const float* __restrict__ g_in,
                      const float* __restrict__ V_mid, const float* __restrict__ g_mid,
                      const float* __restrict__ V_out, const float* __restrict__ g_out) {
    const int blk  = blockIdx.x;
    const int tid  = threadIdx.x;
    const int wid  = tid >> 5;
    const int lane = tid & 31;

    if (blk < NB_SCAT) {
        __shared__ int lh[NC], base[NC];
        if (tid < NC) lh[tid] = 0;
        __syncthreads();
        int i = blk * 256 + tid;
        int c = -1, r = 0;
        if (i < n) { c = cid[i]; r = atomicAdd(&lh[c], 1); }
        __syncthreads();
        if (tid < NC) base[tid] = atomicAdd(&d_cursor[tid], lh[tid]);
        __syncthreads();
        if (i < n) d_sortedPad[c * NMAX + base[c] + r] = i;
        return;
    }
    if (blk < NB_SCAT + NB_MID) {
        int row = (blk - NB_SCAT) * 8 + wid;         // [0, 6144)
        int c = row / (NMID * HD);
        int l = (row / HD) % NMID;
        int r = row & (HD - 1);
        const float* v = V_mid + (size_t)row * HD;
        float vals[8];
        float s = 0.f;
        #pragma unroll
        for (int j = 0; j < 8; j++) { vals[j] = v[lane + 32 * j]; s = fmaf(vals[j], vals[j], s); }
        #pragma unroll
        for (int off = 16; off; off >>= 1) s += __shfl_xor_sync(0xffffffffu, s, off);
        float scale = g_mid[row] * rsqrtf(s);
        #pragma unroll
        for (int j = 0; j < 8; j++) {
            float w = vals[j] * scale;
            __nv_bfloat16 hi = __float2bfloat16(w);
            __nv_bfloat16 lo = __float2bfloat16(w - __bfloat162float(hi));
            int ci = l * 8 + j;
            size_t base = (size_t)(c * NCHUNK + ci) * CHUNK_BYTES + (size_t)r * BROW + (size_t)lane * 2;
            *reinterpret_cast<__nv_bfloat16*>(d_Wpk + base)           = hi;
            *reinterpret_cast<__nv_bfloat16*>(d_Wpk + base + CHUNK_B) = lo;
        }
        return;
    }
    if (blk < NB_SCAT + NB_MID + NB_WIN) {
        int row = (blk - NB_SCAT - NB_MID) * 8 + wid;   // [0, 2048)
        const float* v = V_in + (size_t)row * DIN;
        float v0 = v[lane];
        float v1 = (lane < DIN - 32) ? v[32 + lane] : 0.f;
        float s = fmaf(v0, v0, v1 * v1);
        #pragma unroll
        for (int off = 16; off; off >>= 1) s += __shfl_xor_sync(0xffffffffu, s, off);
        float scale = g_in[row] * rsqrtf(s);
        d_Win[row * DIN + lane] = v0 * scale;
        if (lane < DIN - 32) d_Win[row * DIN + 32 + lane] = v1 * scale;
        return;
    }
    {
        #pragma unroll
        for (int it = 0; it < 3; it++) {
            int row = wid * 3 + it;                    // [0, 24)
            const float* v = V_out + (size_t)row * HD;
            float vals[8];
            float s = 0.f;
            #pragma unroll
            for (int j = 0; j < 8; j++) { vals[j] = v[lane + 32 * j]; s = fmaf(vals[j], vals[j], s); }
            #pragma unroll
            for (int off = 16; off; off >>= 1) s += __shfl_xor_sync(0xffffffffu, s, off);
            float scale = g_out[row] * rsqrtf(s);
            #pragma unroll
            for (int j = 0; j < 8; j++) d_Wout[row * HD + lane + 32 * j] = vals[j] * scale;
        }
    }
}

__global__ void prefixK() {
    if (threadIdx.x == 0) {
        int bo = 0;
        for (int c = 0; c < NC; c++) {
            d_blkoff[c] = bo;
            bo += (d_cursor[c] + TM - 1) / TM;
        }
        d_blkoff[NC] = bo;
    }
}

// ---------------- PTX helpers ----------------
__device__ __forceinline__ void cp16(uint32_t s, const void* g) {
    asm volatile("cp.async.cg.shared.global [%0], [%1], 16;" :: "r"(s), "l"(g));
}
__device__ __forceinline__ void cp_commit()  { asm volatile("cp.async.commit_group;"); }
__device__ __forceinline__ void cp_wait1()   { asm volatile("cp.async.wait_group 1;" ::: "memory"); }
__device__ __forceinline__ void cp_wait0()   { asm volatile("cp.async.wait_group 0;" ::: "memory"); }

__device__ __forceinline__ void ldsm4(uint32_t& r0, uint32_t& r1, uint32_t& r2, uint32_t& r3, uint32_t a) {
    asm volatile("ldmatrix.sync.aligned.m8n8.x4.shared.b16 {%0,%1,%2,%3}, [%4];"
                 : "=r"(r0), "=r"(r1), "=r"(r2), "=r"(r3) : "r"(a));
}

__device__ __forceinline__ void mma16816(float* d, const uint32_t* a, uint32_t b0, uint32_t b1) {
    asm volatile("mma.sync.aligned.m16n8k16.row.col.f32.bf16.bf16.f32 "
                 "{%0,%1,%2,%3}, {%4,%5,%6,%7}, {%8,%9}, {%0,%1,%2,%3};"
                 : "+f"(d[0]), "+f"(d[1]), "+f"(d[2]), "+f"(d[3])
                 : "r"(a[0]), "r"(a[1]), "r"(a[2]), "r"(a[3]), "r"(b0), "r"(b1));
}

__device__ __forceinline__ uint32_t pack_hi(float a, float b, float& ra, float& rb) {
    __nv_bfloat16 ah = __float2bfloat16(a);
    __nv_bfloat16 bh = __float2bfloat16(b);
    ra = a - __bfloat162float(ah);
    rb = b - __bfloat162float(bh);
    __nv_bfloat162 h2 = __halves2bfloat162(ah, bh);
    return *reinterpret_cast<uint32_t*>(&h2);
}
__device__ __forceinline__ uint32_t pack_lo(float ra, float rb) {
    __nv_bfloat162 l2 = __floats2bfloat162_rn(ra, rb);
    return *reinterpret_cast<uint32_t*>(&l2);
}

// ---------------- fused MLP: SIMT layer0 + HMMA mid layers ----------------
__global__ void __launch_bounds__(NTHR, 1)
mlpK(const float* __restrict__ X,
     const float* __restrict__ b_in,
     const float* __restrict__ b_mid,
     const float* __restrict__ b_out,
     float* __restrict__ out, int n) {
    extern __shared__ unsigned char smem[];

    int b = blockIdx.x;
    if (b >= d_blkoff[NC]) return;
    int c = 0;
    while (b >= d_blkoff[c + 1]) c++;
    const int tile  = b - d_blkoff[c];
    const int start = tile * TM;
    int cnt = d_cursor[c] - start;
    if (cnt > TM) cnt = TM;
    if (cnt < 0) cnt = 0;

    const int tid  = threadIdx.x;
    const int wid  = tid >> 5;
    const int lane = tid & 31;
    const int gid  = lane >> 2;
    const int tig  = lane & 3;
    const int sel  = lane >> 3;      // ldmatrix matrix selector
    const int r8   = lane & 7;       // ldmatrix row within matrix
    const uint32_t sbase = (uint32_t)__cvta_generic_to_shared(smem);

    float* biasS = (float*)(smem + SM_BIAS);
    float* bInS  = (float*)(smem + SM_BIN);
    float* WoutS = (float*)(smem + SM_WOUT);
    float* boutS = (float*)(smem + SM_BOUT);
    int*   idxS  = (int*)  (smem + SM_IDX);
    float* WsS   = (float*)(smem + SM_WS);   // 256 x 37 fp32
    float* PS    = (float*)(smem + SM_P);    // 128 x 40 fp32

    // ---- stage: biases, Wout, b_in, layer0 weights ----
    for (int s = tid; s < NMID * HD; s += NTHR) {
        biasS[s] = b_mid[c * NMID * HD + s];
        WoutS[s] = d_Wout[c * NMID * HD + s];
    }
    for (int s = tid; s < HD; s += NTHR) bInS[s] = b_in[c * HD + s];
    if (tid < 3) boutS[tid] = b_out[c * NMID + tid];
    for (int s = tid; s < HD * DIN; s += NTHR) {
        int nn = s / DIN, kk = s - nn * DIN;
        WsS[nn * 37 + kk] = d_Win[(c * HD + nn) * DIN + kk];
    }

    // ---- posenc (fp32) into PS ----
    if (tid < TM) {
        const int m = tid;
        const int id = (m < cnt) ? d_sortedPad[c * NMAX + start + m] : -1;
        idxS[m] = id;
        float* row = PS + m * 40;
        if (id >= 0) {
            float x = X[3 * id], y = X[3 * id + 1], z = X[3 * id + 2];
            float f = 1.f;
            #pragma unroll
            for (int fi = 0; fi < 6; fi++) {
                float s0, c0, s1, c1, s2, c2;
                sincosf(x * f, &s0, &c0);
                sincosf(y * f, &s1, &c1);
                sincosf(z * f, &s2, &c2);
                row[fi * 6 + 0] = s0; row[fi * 6 + 1] = s1; row[fi * 6 + 2] = s2;
                row[fi * 6 + 3] = c0; row[fi * 6 + 4] = c1; row[fi * 6 + 5] = c2;
                f *= 2.f;
            }
        } else {
            #pragma unroll
            for (int k = 0; k < DIN; k++) row[k] = 0.f;
        }
    }
    __syncthreads();

    // ---- layer 0: SIMT fp32 gemm ----
    {
        const int tx = tid & 15;
        const int ty = tid >> 4;
        float acc[4][16];
        #pragma unroll
        for (int i = 0; i < 4; i++)
            #pragma unroll
            for (int j = 0; j < 16; j++) acc[i][j] = 0.f;

        #pragma unroll 4
        for (int kk = 0; kk < DIN; kk++) {
            float a0 = PS[(ty * 4 + 0) * 40 + kk];
            float a1 = PS[(ty * 4 + 1) * 40 + kk];
            float a2 = PS[(ty * 4 + 2) * 40 + kk];
            float a3 = PS[(ty * 4 + 3) * 40 + kk];
            #pragma unroll
            for (int jj = 0; jj < 16; jj++) {
                float w = WsS[(tx + 16 * jj) * 37 + kk];
                acc[0][jj] = fmaf(a0, w, acc[0][jj]);
                acc[1][jj] = fmaf(a1, w, acc[1][jj]);
                acc[2][jj] = fmaf(a2, w, acc[2][jj]);
                acc[3][jj] = fmaf(a3, w, acc[3][jj]);
            }
        }
        __syncthreads();   // done reading PS/WsS (region reused by cp.async below)

        #pragma unroll
        for (int jj = 0; jj < 16; jj++) {
            int nn = tx + 16 * jj;
            float bb = bInS[nn];
            #pragma unroll
            for (int ii = 0; ii < 4; ii++) {
                int m = ty * 4 + ii;
                float v = fmaxf(acc[ii][jj] + bb, 0.f);
                __nv_bfloat16 hi = __float2bfloat16(v);
                __nv_bfloat16 lo = __float2bfloat16(v - __bfloat162float(hi));
                *reinterpret_cast<__nv_bfloat16*>(smem + SM_AHI + m * AROW + nn * 2) = hi;
                *reinterpret_cast<__nv_bfloat16*>(smem + SM_ALO + m * AROW + nn * 2) = lo;
            }
        }
    }
    __syncthreads();

    // ---- mid layers: HMMA with ldmatrix fragment loads ----
    const int m_base = (wid & 3) * 32;
    const int n_base = (wid >> 2) * 64;

    // ldmatrix per-lane base offsets (PTX fragment-table order M0..M3):
    // A x4: M0=(rows+0,kb0) M1=(rows+8,kb0) M2=(rows+0,kb16) M3=(rows+8,kb16)
    uint32_t a_off[2];
    #pragma unroll
    for (int im = 0; im < 2; im++)
        a_off[im] = (uint32_t)((m_base + im * 16 + r8 + (sel & 1) * 8) * AROW + (sel >> 1) * 16);
    // B x4: M0=(n+0,kb0) M1=(n+0,kb16) M2=(n+8,kb0) M3=(n+8,kb16)
    uint32_t bg_off[4];
    #pragma unroll
    for (int jg = 0; jg < 4; jg++)
        bg_off[jg] = (uint32_t)((n_base + jg * 16 + r8 + (sel >> 1) * 8) * BROW + (sel & 1) * 16);

    const unsigned char* wsrc = d_Wpk + (size_t)c * NCHUNK * CHUNK_BYTES;

    // prefetch chunk 0 into buffer 0
    {
        const unsigned char* g = wsrc;
        #pragma unroll
        for (int j = 0; j < 5; j++) {
            int o = (tid + j * NTHR) * 16;
            cp16(sbase + SM_B + o, g + o);
        }
        cp_commit();
    }

    int q = 0;

    #pragma unroll 1
    for (int l = 0; l < 3; l++) {
        float D[2][8][4];
        #pragma unroll
        for (int im = 0; im < 2; im++)
            #pragma unroll
            for (int jn = 0; jn < 8; jn++)
                #pragma unroll
                for (int e = 0; e < 4; e++) D[im][jn][e] = 0.f;

        #pragma unroll 1
        for (int i = 0; i < 8; i++) {
            bool pf = (q + 1 < NCHUNK);
            if (pf) {
                const unsigned char* g = wsrc + (size_t)(q + 1) * CHUNK_BYTES;
                uint32_t sb = sbase + SM_B + ((q + 1) & 1) * CHUNK_BYTES;
                #pragma unroll
                for (int j = 0; j < 5; j++) {
                    int o = (tid + j * NTHR) * 16;
                    cp16(sb + o, g + o);
                }
                cp_commit();
                cp_wait1();
            } else {
                cp_wait0();
            }
            __syncthreads();

            const uint32_t bhiA = sbase + SM_B + (uint32_t)(q & 1) * CHUNK_BYTES;
            const uint32_t bloA = bhiA + CHUNK_B;
            const uint32_t kA   = (uint32_t)(i * KCH) * 2;

            #pragma unroll
            for (int ks = 0; ks < 2; ks++) {
                const uint32_t kbA = kA + (uint32_t)ks * 32;
                const uint32_t kbB = (uint32_t)ks * 32;

                // ---- A fragments via ldmatrix (hi + lo) ----
                uint32_t Ahi[2][4], Alo[2][4];
                #pragma unroll
                for (int im = 0; im < 2; im++) {
                    ldsm4(Ahi[im][0], Ahi[im][1], Ahi[im][2], Ahi[im][3],
                          sbase + SM_AHI + a_off[im] + kbA);
                    ldsm4(Alo[im][0], Alo[im][1], Alo[im][2], Alo[im][3],
                          sbase + SM_ALO + a_off[im] + kbA);
                }

                // ---- B-hi fragments via ldmatrix ----
                uint32_t Bf[4][4];
                #pragma unroll
                for (int jg = 0; jg < 4; jg++)
                    ldsm4(Bf[jg][0], Bf[jg][1], Bf[jg][2], Bf[jg][3], bhiA + bg_off[jg] + kbB);

                // s0: Ahi x Bhi
                #pragma unroll
                for (int jg = 0; jg < 4; jg++)
                    #pragma unroll
                    for (int im = 0; im < 2; im++) {
                        mma16816(D[im][jg * 2],     Ahi[im], Bf[jg][0], Bf[jg][1]);
                        mma16816(D[im][jg * 2 + 1], Ahi[im], Bf[jg][2], Bf[jg][3]);
                    }
                // s1: Alo x Bhi
                #pragma unroll
                for (int jg = 0; jg < 4; jg++)
                    #pragma unroll
                    for (int im = 0; im < 2; im++) {
                        mma16816(D[im][jg * 2],     Alo[im], Bf[jg][0], Bf[jg][1]);
                        mma16816(D[im][jg * 2 + 1], Alo[im], Bf[jg][2], Bf[jg][3]);
                    }
                // ---- B-lo fragments (reuse regs) ----
                #pragma unroll
                for (int jg = 0; jg < 4; jg++)
                    ldsm4(Bf[jg][0], Bf[jg][1], Bf[jg][2], Bf[jg][3], bloA + bg_off[jg] + kbB);
                // s2: Ahi x Blo
                #pragma unroll
                for (int jg = 0; jg < 4; jg++)
                    #pragma unroll
                    for (int im = 0; im < 2; im++) {
                        mma16816(D[im][jg * 2],     Ahi[im], Bf[jg][0], Bf[jg][1]);
                        mma16816(D[im][jg * 2 + 1], Ahi[im], Bf[jg][2], Bf[jg][3]);
                    }
            }
            __syncthreads();
            q++;
        }

        // ---- epilogue ----
        const float* bias = biasS + l * HD;
        if (l < 2) {
            #pragma unroll
            for (int im = 0; im < 2; im++) {
                #pragma unroll
                for (int jn = 0; jn < 8; jn++) {
                    int ncol = n_base + jn * 8 + tig * 2;
                    float b0 = bias[ncol], b1 = bias[ncol + 1];
                    #pragma unroll
                    for (int h = 0; h < 2; h++) {
                        int m = m_base + im * 16 + gid + h * 8;
                        float v0 = fmaxf(D[im][jn][2 * h]     + b0, 0.f);
                        float v1 = fmaxf(D[im][jn][2 * h + 1] + b1, 0.f);
                        float ra, rb;
                        uint32_t ph = pack_hi(v0, v1, ra, rb);
                        uint32_t pl = pack_lo(ra, rb);
                        *(uint32_t*)(smem + SM_AHI + m * AROW + ncol * 2) = ph;
                        *(uint32_t*)(smem + SM_ALO + m * AROW + ncol * 2) = pl;
                    }
                }
            }
            __syncthreads();
        } else {
            // final hidden -> fp32 h, row stride HROW=264 floats (fits A region)
            float* hbuf = (float*)(smem + SM_AHI);
            #pragma unroll
            for (int im = 0; im < 2; im++) {
                #pragma unroll
                for (int jn = 0; jn < 8; jn++) {
                    int ncol = n_base + jn * 8 + tig * 2;
                    float b0 = bias[ncol], b1 = bias[ncol + 1];
                    #pragma unroll
                    for (int h = 0; h < 2; h++) {
                        int m = m_base + im * 16 + gid + h * 8;
                        float v0 = fmaxf(D[im][jn][2 * h]     + b0, 0.f);
                        float v1 = fmaxf(D[im][jn][2 * h + 1] + b1, 0.f);
                        float2* p = (float2*)(hbuf + m * HROW + ncol);
                        *p = make_float2(v0, v1);
                    }
                }
            }
            __syncthreads();
            // fused output layer: 384 (m,j) dots of length 256
            const float* hb = (const float*)(smem + SM_AHI);
            #pragma unroll
            for (int qq = 0; qq < 24; qq++) {
                int o = wid * 24 + qq;
                int m = o / 3, j = o - 3 * m;
                const float* hr = hb + m * HROW;
                const float* wr = WoutS + j * HD;
                float s = 0.f;
                #pragma unroll
                for (int k = lane; k < HD; k += 32) s = fmaf(hr[k], wr[k], s);
                #pragma unroll
                for (int off = 16; off; off >>= 1) s += __shfl_xor_sync(0xffffffffu, s, off);
                if (lane == 0) {
                    int id = idxS[m];
                    if (id >= 0) out[3 * id + j] = tanhf(s + boutS[j]);
                }
            }
        }
    }
}

// ---------------- launch ----------------
extern "C" void kernel_launch(void* const* d_in, const int* in_sizes, int n_in,
                              void* d_out, int out_size) {
    const float* X     = (const float*)d_in[0];
    const int*   cid   = (const int*)  d_in[1];
    const float* V_in  = (const float*)d_in[2];
    const float* g_in  = (const float*)d_in[3];
    const float* b_in  = (const float*)d_in[4];
    const float* V_mid = (const float*)d_in[5];
    const float* g_mid = (const float*)d_in[6];
    const float* b_mid = (const float*)d_in[7];
    const float* V_out = (const float*)d_in[8];
    const float* g_out = (const float*)d_in[9];
    const float* b_out = (const float*)d_in[10];
    float* out = (float*)d_out;
    const int n = in_sizes[0] / 3;

    cudaFuncSetAttribute(mlpK, cudaFuncAttributeMaxDynamicSharedMemorySize, SMEM_BYTES);

    initK<<<1, 32>>>();
    prepK<<<NB_PREP, 256>>>(cid, n, V_in, g_in, V_mid, g_mid, V_out, g_out);
    prefixK<<<1, 1>>>();

    const int blocks = (n + TM - 1) / TM + NC;
    mlpK<<<blocks, NTHR, SMEM_BYTES>>>(X, b_in, b_mid, b_out, out, n);
}

// round 9
// speedup vs baseline: 4.8817x; 1.2142x over previous
#include <cuda_runtime.h>
#include <cuda_bf16.h>
#include <math.h>
#include <stdint.h>

// ---------------- problem constants ----------------
#define NC    8
#define HD    256
#define DIN   36
#define NMID  3
#define NMAX  65536
#define TM    64           // points per CTA
#define NTHR  256          // 8 warps: 2 (m) x 4 (n)

#define BROW2     48       // chunk row stride bytes (12 words, conflict-free ldmatrix)
#define CHUNK2    12288    // 256 rows x 48B: one kstep (k16), one split
#define NRING     3
#define NKSTEP    51       // 3 (layer0 K=48) + 3*16 (mid layers K=256)
#define NCHUNKS   102      // 2 chunks (hi,lo) per kstep
#define AROW      528      // A SMEM row stride bytes (132 words, conflict-free)
#define HROW      264      // final fp32 hidden row stride (floats): 64*264*4 = 67584 = A region

// SMEM layout (bytes)
#define SM_AHI   0
#define SM_ALO   (SM_AHI + TM * AROW)            // 33792
#define SM_B     (SM_ALO + TM * AROW)            // 67584  (ring: 3 x 12288)
#define SM_BIAS  (SM_B + NRING * CHUNK2)         // 104448 (4*256 floats: b_in + 3 mid)
#define SM_WOUT  (SM_BIAS + 4 * HD * 4)          // 108544 (3*256 floats)
#define SM_BOUT  (SM_WOUT + 3 * HD * 4)          // 111616 (4 floats)
#define SM_IDX   (SM_BOUT + 16)                  // 111632 (64 ints)
#define SMEM_BYTES (SM_IDX + TM * 4)             // 111888

// prep kernel block ranges
#define NB_SCAT  256
#define NB_MID   768      // 6144 mid rows / 8 warps
#define NB_WIN   256      // 2048 win rows / 8 warps
#define NB_WOUT  1
#define NB_PREP  (NB_SCAT + NB_MID + NB_WIN + NB_WOUT)

// ---------------- device scratch ----------------
__device__ float d_Wout[NC * NMID * HD];
__device__ __align__(128) unsigned char d_Wpk[NC * NCHUNKS * CHUNK2];  // ~10 MB
__device__ int   d_sortedPad[NC * NMAX];
__device__ int   d_cursor[NC];
__device__ int   d_blkoff[NC + 1];

// ---------------- helpers ----------------
__device__ __forceinline__ void split_w(float w, __nv_bfloat16& hi, __nv_bfloat16& lo) {
    hi = __float2bfloat16(w);
    lo = __float2bfloat16(w - __bfloat162float(hi));
}

// ---------------- setup kernels ----------------
__global__ void initK() { if (threadIdx.x < NC) d_cursor[threadIdx.x] = 0; }

__global__ void prepK(const int* __restrict__ cid, int n,
                      const float* __restrict__ V_in,  const float* __restrict__ g_in,
                      const float* __restrict__ V_mid, const float* __restrict__ g_mid,
                      const float* __restrict__ V_out, const float* __restrict__ g_out) {
    const int blk  = blockIdx.x;
    const int tid  = threadIdx.x;
    const int wid  = tid >> 5;
    const int lane = tid & 31;

    if (blk < NB_SCAT) {
        __shared__ int lh[NC], base[NC];
        if (tid < NC) lh[tid] = 0;
        __syncthreads();
        int i = blk * 256 + tid;
        int c = -1, r = 0;
        if (i < n) { c = cid[i]; r = atomicAdd(&lh[c], 1); }
        __syncthreads();
        if (tid < NC) base[tid] = atomicAdd(&d_cursor[tid], lh[tid]);
        __syncthreads();
        if (i < n) d_sortedPad[c * NMAX + base[c] + r] = i;
        return;
    }
    if (blk < NB_SCAT + NB_MID) {
        // mid weights: norm + split-bf16 into per-kstep chunks
        int row = (blk - NB_SCAT) * 8 + wid;         // [0, 6144)
        int c = row / (NMID * HD);
        int l = (row / HD) % NMID;
        int r = row & (HD - 1);
        const float* v = V_mid + (size_t)row * HD;
        float vals[8];
        float s = 0.f;
        #pragma unroll
        for (int j = 0; j < 8; j++) { vals[j] = v[lane + 32 * j]; s = fmaf(vals[j], vals[j], s); }
        #pragma unroll
        for (int off = 16; off; off >>= 1) s += __shfl_xor_sync(0xffffffffu, s, off);
        float scale = g_mid[row] * rsqrtf(s);
        #pragma unroll
        for (int j = 0; j < 8; j++) {
            float w = vals[j] * scale;
            __nv_bfloat16 hi, lo; split_w(w, hi, lo);
            int k = lane + 32 * j;
            int kstep = 3 + l * 16 + (k >> 4);
            size_t ba = (size_t)(c * NCHUNKS + 2 * kstep) * CHUNK2 + (size_t)r * BROW2 + (size_t)(k & 15) * 2;
            *reinterpret_cast<__nv_bfloat16*>(d_Wpk + ba)          = hi;
            *reinterpret_cast<__nv_bfloat16*>(d_Wpk + ba + CHUNK2) = lo;
        }
        return;
    }
    if (blk < NB_SCAT + NB_MID + NB_WIN) {
        // layer-0 weights: norm + split-bf16 into chunks (K padded 36 -> 48)
        int row = (blk - NB_SCAT - NB_MID) * 8 + wid;   // [0, 2048)
        int c = row >> 8;
        int r = row & 255;
        const float* v = V_in + (size_t)row * DIN;
        float v0 = v[lane];
        float v1 = (lane < DIN - 32) ? v[32 + lane] : 0.f;
        float s = fmaf(v0, v0, v1 * v1);
        #pragma unroll
        for (int off = 16; off; off >>= 1) s += __shfl_xor_sync(0xffffffffu, s, off);
        float scale = g_in[row] * rsqrtf(s);
        // write k = lane and k = lane+32 (zero-padded beyond DIN)
        #pragma unroll
        for (int half = 0; half < 2; half++) {
            int k = lane + 32 * half;
            if (k >= 48) continue;
            float w = (k < 32) ? v0 * scale : ((k < DIN) ? v1 * scale : 0.f);
            __nv_bfloat16 hi, lo; split_w(w, hi, lo);
            int kstep = k >> 4;
            size_t ba = (size_t)(c * NCHUNKS + 2 * kstep) * CHUNK2 + (size_t)r * BROW2 + (size_t)(k & 15) * 2;
            *reinterpret_cast<__nv_bfloat16*>(d_Wpk + ba)          = hi;
            *reinterpret_cast<__nv_bfloat16*>(d_Wpk + ba + CHUNK2) = lo;
        }
        return;
    }
    {
        #pragma unroll
        for (int it = 0; it < 3; it++) {
            int row = wid * 3 + it;                    // [0, 24)
            const float* v = V_out + (size_t)row * HD;
            float vals[8];
            float s = 0.f;
            #pragma unroll
            for (int j = 0; j < 8; j++) { vals[j] = v[lane + 32 * j]; s = fmaf(vals[j], vals[j], s); }
            #pragma unroll
            for (int off = 16; off; off >>= 1) s += __shfl_xor_sync(0xffffffffu, s, off);
            float scale = g_out[row] * rsqrtf(s);
            #pragma unroll
            for (int j = 0; j < 8; j++) d_Wout[row * HD + lane + 32 * j] = vals[j] * scale;
        }
    }
}

__global__ void prefixK() {
    if (threadIdx.x == 0) {
        int bo = 0;
        for (int c = 0; c < NC; c++) {
            d_blkoff[c] = bo;
            bo += (d_cursor[c] + TM - 1) / TM;
        }
        d_blkoff[NC] = bo;
    }
}

// ---------------- PTX helpers ----------------
__device__ __forceinline__ void cp16(uint32_t s, const void* g) {
    asm volatile("cp.async.cg.shared.global [%0], [%1], 16;" :: "r"(s), "l"(g));
}
__device__ __forceinline__ void cp_commit()  { asm volatile("cp.async.commit_group;"); }
__device__ __forceinline__ void cp_wait1()   { asm volatile("cp.async.wait_group 1;" ::: "memory"); }

__device__ __forceinline__ void ldsm4(uint32_t& r0, uint32_t& r1, uint32_t& r2, uint32_t& r3, uint32_t a) {
    asm volatile("ldmatrix.sync.aligned.m8n8.x4.shared.b16 {%0,%1,%2,%3}, [%4];"
                 : "=r"(r0), "=r"(r1), "=r"(r2), "=r"(r3) : "r"(a));
}

__device__ __forceinline__ void mma16816(float* d, const uint32_t* a, uint32_t b0, uint32_t b1) {
    asm volatile("mma.sync.aligned.m16n8k16.row.col.f32.bf16.bf16.f32 "
                 "{%0,%1,%2,%3}, {%4,%5,%6,%7}, {%8,%9}, {%0,%1,%2,%3};"
                 : "+f"(d[0]), "+f"(d[1]), "+f"(d[2]), "+f"(d[3])
                 : "r"(a[0]), "r"(a[1]), "r"(a[2]), "r"(a[3]), "r"(b0), "r"(b1));
}

__device__ __forceinline__ uint32_t pack_hi(float a, float b, float& ra, float& rb) {
    __nv_bfloat16 ah = __float2bfloat16(a);
    __nv_bfloat16 bh = __float2bfloat16(b);
    ra = a - __bfloat162float(ah);
    rb = b - __bfloat162float(bh);
    __nv_bfloat162 h2 = __halves2bfloat162(ah, bh);
    return *reinterpret_cast<uint32_t*>(&h2);
}
__device__ __forceinline__ uint32_t pack_lo(float ra, float rb) {
    __nv_bfloat162 l2 = __floats2bfloat162_rn(ra, rb);
    return *reinterpret_cast<uint32_t*>(&l2);
}

// ---------------- fused MLP: all-MMA (layer0 + mids), 2 CTAs/SM ----------------
__global__ void __launch_bounds__(NTHR, 2)
mlpK(const float* __restrict__ X,
     const float* __restrict__ b_in,
     const float* __restrict__ b_mid,
     const float* __restrict__ b_out,
     float* __restrict__ out, int n) {
    extern __shared__ unsigned char smem[];

    int b = blockIdx.x;
    if (b >= d_blkoff[NC]) return;
    int c = 0;
    while (b >= d_blkoff[c + 1]) c++;
    const int start = (b - d_blkoff[c]) * TM;
    int cnt = d_cursor[c] - start;
    if (cnt > TM) cnt = TM;
    if (cnt < 0) cnt = 0;

    const int tid  = threadIdx.x;
    const int wid  = tid >> 5;
    const int lane = tid & 31;
    const int gid  = lane >> 2;
    const int tig  = lane & 3;
    const int sel  = lane >> 3;
    const int r8   = lane & 7;
    const uint32_t sbase = (uint32_t)__cvta_generic_to_shared(smem);

    float* biasS = (float*)(smem + SM_BIAS);
    float* WoutS = (float*)(smem + SM_WOUT);
    float* boutS = (float*)(smem + SM_BOUT);
    int*   idxS  = (int*)  (smem + SM_IDX);

    // ---- stage biases / Wout / bout ----
    #pragma unroll
    for (int it = 0; it < 4; it++) {
        int s = tid + it * NTHR;            // [0,1024)
        float v;
        if (s < HD) v = b_in[c * HD + s];
        else        v = b_mid[(c * NMID + (s / HD - 1)) * HD + (s & (HD - 1))];
        biasS[s] = v;
    }
    #pragma unroll
    for (int it = 0; it < 3; it++) {
        int s = tid + it * NTHR;
        WoutS[s] = d_Wout[c * NMID * HD + s];
    }
    if (tid < 3) boutS[tid] = b_out[c * NMID + tid];

    // ---- posenc -> split-bf16 A image (K padded to 48, cols 36..47 zero) ----
    if (tid < TM) {
        const int m = tid;
        const int id = (m < cnt) ? d_sortedPad[c * NMAX + start + m] : -1;
        idxS[m] = id;
        float e[36];
        #pragma unroll
        for (int k = 0; k < 36; k++) e[k] = 0.f;
        if (id >= 0) {
            float x = X[3 * id], y = X[3 * id + 1], z = X[3 * id + 2];
            float f = 1.f;
            #pragma unroll
            for (int fi = 0; fi < 6; fi++) {
                float s0, c0, s1, c1, s2, c2;
                sincosf(x * f, &s0, &c0);
                sincosf(y * f, &s1, &c1);
                sincosf(z * f, &s2, &c2);
                e[fi * 6 + 0] = s0; e[fi * 6 + 1] = s1; e[fi * 6 + 2] = s2;
                e[fi * 6 + 3] = c0; e[fi * 6 + 4] = c1; e[fi * 6 + 5] = c2;
                f *= 2.f;
            }
        }
        uint32_t* hi = (uint32_t*)(smem + SM_AHI + m * AROW);
        uint32_t* lo = (uint32_t*)(smem + SM_ALO + m * AROW);
        #pragma unroll
        for (int i = 0; i < 18; i++) {
            float ra, rb;
            hi[i] = pack_hi(e[2 * i], e[2 * i + 1], ra, rb);
            lo[i] = pack_lo(ra, rb);
        }
        #pragma unroll
        for (int i = 18; i < 24; i++) { hi[i] = 0u; lo[i] = 0u; }
    }

    // warp tiling: 2 (m) x 4 (n)
    const int m_base = (wid & 1) * 32;
    const int n_base = (wid >> 1) * 64;

    uint32_t a_off[2];
    #pragma unroll
    for (int im = 0; im < 2; im++)
        a_off[im] = (uint32_t)((m_base + im * 16 + r8 + (sel & 1) * 8) * AROW + (sel >> 1) * 16);
    uint32_t bg_off[4];
    #pragma unroll
    for (int jg = 0; jg < 4; jg++)
        bg_off[jg] = (uint32_t)((n_base + jg * 16 + r8 + (sel >> 1) * 8) * BROW2 + (sel & 1) * 16);

    const unsigned char* wsrc = d_Wpk + (size_t)c * NCHUNKS * CHUNK2;

    // prefetch chunks 0, 1 into ring slots 0, 1
    #pragma unroll
    for (int pc = 0; pc < 2; pc++) {
        const unsigned char* g = wsrc + (size_t)pc * CHUNK2;
        uint32_t sb = sbase + SM_B + pc * CHUNK2;
        #pragma unroll
        for (int j = 0; j < 3; j++) {
            int o = tid * 16 + j * 4096;
            cp16(sb + o, g + o);
        }
        cp_commit();
    }

    int q = 0;

    #pragma unroll 1
    for (int l = 0; l < 4; l++) {
        float D[2][8][4];
        #pragma unroll
        for (int im = 0; im < 2; im++)
            #pragma unroll
            for (int jn = 0; jn < 8; jn++)
                #pragma unroll
                for (int e = 0; e < 4; e++) D[im][jn][e] = 0.f;

        const int nk = (l == 0) ? 3 : 16;
        #pragma unroll 1
        for (int t = 0; t < nk; t++) {
            uint32_t Ahi[2][4], Alo[2][4], Bf[4][4];
            const uint32_t kbA = (uint32_t)t * 32;

            // ---- hi chunk q ----
            cp_wait1();
            __syncthreads();
            {
                // prefetch chunk q+2 into slot freed at q-1
                if (q + 2 < NCHUNKS) {
                    const unsigned char* g = wsrc + (size_t)(q + 2) * CHUNK2;
                    uint32_t sb = sbase + SM_B + ((q + 2) % NRING) * CHUNK2;
                    #pragma unroll
                    for (int j = 0; j < 3; j++) {
                        int o = tid * 16 + j * 4096;
                        cp16(sb + o, g + o);
                    }
                }
                cp_commit();

                const uint32_t bA = sbase + SM_B + (uint32_t)(q % NRING) * CHUNK2;
                #pragma unroll
                for (int im = 0; im < 2; im++) {
                    ldsm4(Ahi[im][0], Ahi[im][1], Ahi[im][2], Ahi[im][3],
                          sbase + SM_AHI + a_off[im] + kbA);
                    ldsm4(Alo[im][0], Alo[im][1], Alo[im][2], Alo[im][3],
                          sbase + SM_ALO + a_off[im] + kbA);
                }
                #pragma unroll
                for (int jg = 0; jg < 4; jg++)
                    ldsm4(Bf[jg][0], Bf[jg][1], Bf[jg][2], Bf[jg][3], bA + bg_off[jg]);

                // s0: Ahi x Bhi
                #pragma unroll
                for (int jg = 0; jg < 4; jg++)
                    #pragma unroll
                    for (int im = 0; im < 2; im++) {
                        mma16816(D[im][jg * 2],     Ahi[im], Bf[jg][0], Bf[jg][1]);
                        mma16816(D[im][jg * 2 + 1], Ahi[im], Bf[jg][2], Bf[jg][3]);
                    }
                // s1: Alo x Bhi
                #pragma unroll
                for (int jg = 0; jg < 4; jg++)
                    #pragma unroll
                    for (int im = 0; im < 2; im++) {
                        mma16816(D[im][jg * 2],     Alo[im], Bf[jg][0], Bf[jg][1]);
                        mma16816(D[im][jg * 2 + 1], Alo[im], Bf[jg][2], Bf[jg][3]);
                    }
            }
            q++;

            // ---- lo chunk q ----
            cp_wait1();
            __syncthreads();
            {
                if (q + 2 < NCHUNKS) {
                    const unsigned char* g = wsrc + (size_t)(q + 2) * CHUNK2;
                    uint32_t sb = sbase + SM_B + ((q + 2) % NRING) * CHUNK2;
                    #pragma unroll
                    for (int j = 0; j < 3; j++) {
                        int o = tid * 16 + j * 4096;
                        cp16(sb + o, g + o);
                    }
                }
                cp_commit();

                const uint32_t bA = sbase + SM_B + (uint32_t)(q % NRING) * CHUNK2;
                #pragma unroll
                for (int jg = 0; jg < 4; jg++)
                    ldsm4(Bf[jg][0], Bf[jg][1], Bf[jg][2], Bf[jg][3], bA + bg_off[jg]);

                // s2: Ahi x Blo
                #pragma unroll
                for (int jg = 0; jg < 4; jg++)
                    #pragma unroll
                    for (int im = 0; im < 2; im++) {
                        mma16816(D[im][jg * 2],     Ahi[im], Bf[jg][0], Bf[jg][1]);
                        mma16816(D[im][jg * 2 + 1], Ahi[im], Bf[jg][2], Bf[jg][3]);
                    }
            }
            q++;
        }

        // ---- epilogue (barrier first: all warps must be done reading A) ----
        __syncthreads();
        const float* bias = biasS + l * HD;
        if (l < 3) {
            #pragma unroll
            for (int im = 0; im < 2; im++) {
                #pragma unroll
                for (int jn = 0; jn < 8; jn++) {
                    int ncol = n_base + jn * 8 + tig * 2;
                    float b0 = bias[ncol], b1 = bias[ncol + 1];
                    #pragma unroll
                    for (int h = 0; h < 2; h++) {
                        int m = m_base + im * 16 + gid + h * 8;
                        float v0 = fmaxf(D[im][jn][2 * h]     + b0, 0.f);
                        float v1 = fmaxf(D[im][jn][2 * h + 1] + b1, 0.f);
                        float ra, rb;
                        uint32_t ph = pack_hi(v0, v1, ra, rb);
                        uint32_t pl = pack_lo(ra, rb);
                        *(uint32_t*)(smem + SM_AHI + m * AROW + ncol * 2) = ph;
                        *(uint32_t*)(smem + SM_ALO + m * AROW + ncol * 2) = pl;
                    }
                }
            }
        } else {
            // final hidden -> fp32 h in A region (HROW floats per row)
            float* hbuf = (float*)(smem + SM_AHI);
            #pragma unroll
            for (int im = 0; im < 2; im++) {
                #pragma unroll
                for (int jn = 0; jn < 8; jn++) {
                    int ncol = n_base + jn * 8 + tig * 2;
                    float b0 = bias[ncol], b1 = bias[ncol + 1];
                    #pragma unroll
                    for (int h = 0; h < 2; h++) {
                        int m = m_base + im * 16 + gid + h * 8;
                        float v0 = fmaxf(D[im][jn][2 * h]     + b0, 0.f);
                        float v1 = fmaxf(D[im][jn][2 * h + 1] + b1, 0.f);
                        float2* p = (float2*)(hbuf + m * HROW + ncol);
                        *p = make_float2(v0, v1);
                    }
                }
            }
            __syncthreads();
            // fused output layer: 192 (m,j) dots of length 256
            const float* hb = (const float*)(smem + SM_AHI);
            #pragma unroll
            for (int qq = 0; qq < 24; qq++) {
                int o = wid * 24 + qq;
                int m = o / 3, j = o - 3 * m;
                const float* hr = hb + m * HROW;
                const float* wr = WoutS + j * HD;
                float s = 0.f;
                #pragma unroll
                for (int k = lane; k < HD; k += 32) s = fmaf(hr[k], wr[k], s);
                #pragma unroll
                for (int off = 16; off; off >>= 1) s += __shfl_xor_sync(0xffffffffu, s, off);
                if (lane == 0) {
                    int id = idxS[m];
                    if (id >= 0) out[3 * id + j] = tanhf(s + boutS[j]);
                }
            }
        }
    }
}

// ---------------- launch ----------------
extern "C" void kernel_launch(void* const* d_in, const int* in_sizes, int n_in,
                              void* d_out, int out_size) {
    const float* X     = (const float*)d_in[0];
    const int*   cid   = (const int*)  d_in[1];
    const float* V_in  = (const float*)d_in[2];
    const float* g_in  = (const float*)d_in[3];
    const float* b_in  = (const float*)d_in[4];
    const float* V_mid = (const float*)d_in[5];
    const float* g_mid = (const float*)d_in[6];
    const float* b_mid = (const float*)d_in[7];
    const float* V_out = (const float*)d_in[8];
    const float* g_out = (const float*)d_in[9];
    const float* b_out = (const float*)d_in[10];
    float* out = (float*)d_out;
    const int n = in_sizes[0] / 3;

    cudaFuncSetAttribute(mlpK, cudaFuncAttributeMaxDynamicSharedMemorySize, SMEM_BYTES);

    initK<<<1, 32>>>();
    prepK<<<NB_PREP, 256>>>(cid, n, V_in, g_in, V_mid, g_mid, V_out, g_out);
    prefixK<<<1, 1>>>();

    const int blocks = (n + TM - 1) / TM + NC;
    mlpK<<<blocks, NTHR, SMEM_BYTES>>>(X, b_in, b_mid, b_out, out, n);
}